// round 11
// baseline (speedup 1.0000x reference)
#include <cuda_runtime.h>
#include <cuda_fp16.h>
#include <cstdint>

#define BB   32
#define TT   64
#define EE   256
#define UU   512
#define DD   512
#define VV   32000
#define NTOK 2048
#define G4U  2048
#define G2U  1024
#define NTILES 4000          // (2048/128) * (32000/128)

// ---------------- scratch ----------------
__device__ float  g_xe   [NTOK * EE];
__device__ float  g_Zf   [NTOK * G4U];
__device__ float  g_Zb   [NTOK * G4U];
__device__ float  g_a    [NTOK * G2U];
__device__ __half g_aH   [NTOK * G2U];
__device__ __half g_aW1H [NTOK * 12];
__device__ __half g_aWxdH[NTOK * G4U];
__device__ __half g_HdH  [NTOK * DD];
__device__ __half g_WoH  [VV * DD];
__device__ __half g_W1TH [10 * 512];
__device__ float  g_rowsum[NTOK];
// barrier state
__device__ int    g_ectr[2][64];   // 8 counters x 8-int spacing, per dir
__device__ int    g_ego2[2];
__device__ int    g_efin[2];
__device__ int    g_dctr[64];
__device__ int    g_dgo2;
__device__ int    g_dall;
__device__ int    g_tile;
__device__ int    g_gfin;

__device__ __forceinline__ float sigf(float x) { return 1.f / (1.f + __expf(-x)); }
__device__ __forceinline__ float tanh_fast(float x) {
    float r; asm("tanh.approx.f32 %0, %1;" : "=f"(r) : "f"(x)); return r;
}
__device__ __forceinline__ int ld_acq(const int* p) {
    int v; asm volatile("ld.acquire.gpu.global.b32 %0, [%1];" : "=r"(v) : "l"(p) : "memory");
    return v;
}
__device__ __forceinline__ int ld_rlx(const int* p) {
    int v; asm volatile("ld.relaxed.gpu.global.b32 %0, [%1];" : "=r"(v) : "l"(p) : "memory");
    return v;
}
__device__ __forceinline__ void red_rel(int* p) {
    asm volatile("red.release.gpu.global.add.s32 [%0], 1;" :: "l"(p) : "memory");
}
__device__ __forceinline__ void st_rel(int* p, int v) {
    asm volatile("st.release.gpu.global.b32 [%0], %1;" :: "l"(p), "r"(v) : "memory");
}

// spread-counter barrier: arrivals hit 8 counters; leader sum-polls and broadcasts go=step
__device__ __forceinline__ void bar_fast(int* ctr, int* go, int step, int grp, bool lead) {
    __syncthreads();
    if (threadIdx.x == 0) {
        red_rel(&ctr[grp * 8]);
        if (lead) {
            int need = step * 64;
            int s;
            do {
                s = 0;
#pragma unroll
                for (int i = 0; i < 8; i++) s += ld_rlx(&ctr[i * 8]);
            } while (s < need);
            asm volatile("fence.acq_rel.gpu;" ::: "memory");
            st_rel(go, step);
        } else {
            while (ld_acq(go) < step) { }
        }
    }
    __syncthreads();
}

__device__ __forceinline__ void mma8(float* c, uint32_t a0, uint32_t a1, uint32_t a2, uint32_t a3,
                                     uint32_t b0, uint32_t b1) {
    asm volatile(
        "mma.sync.aligned.m16n8k8.row.col.f32.tf32.tf32.f32 "
        "{%0,%1,%2,%3}, {%4,%5,%6,%7}, {%8,%9}, {%0,%1,%2,%3};\n"
        : "+f"(c[0]), "+f"(c[1]), "+f"(c[2]), "+f"(c[3])
        : "r"(a0), "r"(a1), "r"(a2), "r"(a3), "r"(b0), "r"(b1));
}
__device__ __forceinline__ void mma16h(float* c, uint32_t a0, uint32_t a1, uint32_t a2, uint32_t a3,
                                       uint32_t b0, uint32_t b1) {
    asm volatile(
        "mma.sync.aligned.m16n8k16.row.col.f32.f16.f16.f32 "
        "{%0,%1,%2,%3}, {%4,%5,%6,%7}, {%8,%9}, {%0,%1,%2,%3};\n"
        : "+f"(c[0]), "+f"(c[1]), "+f"(c[2]), "+f"(c[3])
        : "r"(a0), "r"(a1), "r"(a2), "r"(a3), "r"(b0), "r"(b1));
}
__device__ __forceinline__ uint32_t lds32(const __half* p) { return *(const uint32_t*)p; }

// ---------------- embedding gather + rowsum zero ----------------
__global__ void k_embed(const int* __restrict__ x, const float* __restrict__ emb) {
    int row = blockIdx.x;
    int t = row >> 5, b = row & 31;
    int tok = x[b * TT + t];
    const float4* src = reinterpret_cast<const float4*>(emb + (size_t)tok * EE);
    float4* dst = reinterpret_cast<float4*>(g_xe + (size_t)row * EE);
    dst[threadIdx.x] = src[threadIdx.x];
    if (threadIdx.x == 0) g_rowsum[row] = 0.f;
}

// ---------------- Wo convert + transpose ----------------
__global__ void k_cvt_wo(const float* __restrict__ Wo) {
    __shared__ float t[32][33];
    int n0 = blockIdx.x << 5, k0 = blockIdx.y << 5;
    for (int i = threadIdx.y; i < 32; i += 8)
        t[i][threadIdx.x] = Wo[(size_t)(k0 + i) * VV + n0 + threadIdx.x];
    __syncthreads();
    for (int i = threadIdx.y; i < 32; i += 8)
        g_WoH[(size_t)(n0 + i) * DD + k0 + threadIdx.x] = __float2half(t[threadIdx.x][i]);
}

// ---------------- W1 decoder-half transpose ----------------
__global__ void k_w1t(const float* __restrict__ W1) {
    int j = blockIdx.x;
    for (int k = threadIdx.x; k < 512; k += blockDim.x)
        g_W1TH[j * 512 + k] = __float2half(W1[(size_t)(G2U + k) * 10 + j]);
}

// ---------------- tf32 GEMM (double-buffered); Ch!=null -> permuted half output ----------------
__global__ __launch_bounds__(256) void k_gemm(
    const float* __restrict__ A, const float* __restrict__ B,
    const float* __restrict__ bias, float* __restrict__ C, __half* __restrict__ Ch,
    int M, int N, int K)
{
    extern __shared__ char gsm[];
    uint32_t (*As)[128][40] = (uint32_t(*)[128][40])gsm;
    uint32_t (*Bs)[32][136] = (uint32_t(*)[32][136])(gsm + 2 * 128 * 40 * 4);
    int tid = threadIdx.x, lane = tid & 31, warp = tid >> 5;
    int gid = lane >> 2, tig = lane & 3;
    int wm = warp & 3, wn = warp >> 2;
    int m0 = blockIdx.y << 7, n0 = blockIdx.x << 7;
    int ntile = K >> 5;
    float acc[2][8][4] = {};

    auto issue = [&](int kt) {
        int st = kt & 1;
        int k0 = kt << 5;
#pragma unroll
        for (int i = 0; i < 4; i++) {
            int idx = tid + (i << 8);
            int r = idx >> 3, c4 = (idx & 7) << 2;
            uint32_t d = (uint32_t)__cvta_generic_to_shared(&As[st][r][c4]);
            const float* s = A + (size_t)(m0 + r) * K + k0 + c4;
            asm volatile("cp.async.cg.shared.global [%0], [%1], 16;\n" :: "r"(d), "l"(s));
        }
#pragma unroll
        for (int i = 0; i < 4; i++) {
            int idx = tid + (i << 8);
            int r = idx >> 5, c4 = (idx & 31) << 2;
            uint32_t d = (uint32_t)__cvta_generic_to_shared(&Bs[st][r][c4]);
            const float* s = B + (size_t)(k0 + r) * N + n0 + c4;
            asm volatile("cp.async.cg.shared.global [%0], [%1], 16;\n" :: "r"(d), "l"(s));
        }
        asm volatile("cp.async.commit_group;\n");
    };

    issue(0);
    for (int kt = 0; kt < ntile; kt++) {
        if (kt + 1 < ntile) { issue(kt + 1); asm volatile("cp.async.wait_group 1;\n"); }
        else                 { asm volatile("cp.async.wait_group 0;\n"); }
        __syncthreads();
        int st = kt & 1;
#pragma unroll
        for (int kk = 0; kk < 32; kk += 8) {
            uint32_t af[2][4];
#pragma unroll
            for (int mt = 0; mt < 2; mt++) {
                int rb = (wm << 5) + (mt << 4);
                af[mt][0] = As[st][rb + gid    ][kk + tig];
                af[mt][1] = As[st][rb + gid + 8][kk + tig];
                af[mt][2] = As[st][rb + gid    ][kk + tig + 4];
                af[mt][3] = As[st][rb + gid + 8][kk + tig + 4];
            }
#pragma unroll
            for (int nt = 0; nt < 8; nt++) {
                uint32_t b0 = Bs[st][kk + tig    ][(wn << 6) + (nt << 3) + gid];
                uint32_t b1 = Bs[st][kk + tig + 4][(wn << 6) + (nt << 3) + gid];
#pragma unroll
                for (int mt = 0; mt < 2; mt++)
                    mma8(acc[mt][nt], af[mt][0], af[mt][1], af[mt][2], af[mt][3], b0, b1);
            }
        }
        __syncthreads();
    }
#pragma unroll
    for (int mt = 0; mt < 2; mt++) {
#pragma unroll
        for (int nt = 0; nt < 8; nt++) {
            int col = n0 + (wn << 6) + (nt << 3) + (tig << 1);
            int r0 = m0 + (wm << 5) + (mt << 4) + gid;
            int r1 = r0 + 8;
            if (Ch) {
                int d = col & 511, gate = col >> 9;
                int nc = ((d >> 3) << 5) + (gate << 3) + (d & 7);
                *reinterpret_cast<__half2*>(Ch + (size_t)r0 * N + nc) =
                    __floats2half2_rn(acc[mt][nt][0], acc[mt][nt][1]);
                *reinterpret_cast<__half2*>(Ch + (size_t)r1 * N + nc) =
                    __floats2half2_rn(acc[mt][nt][2], acc[mt][nt][3]);
            } else {
                float b0v = bias ? bias[col]     : 0.f;
                float b1v = bias ? bias[col + 1] : 0.f;
                float2 v0 = make_float2(acc[mt][nt][0] + b0v, acc[mt][nt][1] + b1v);
                float2 v1 = make_float2(acc[mt][nt][2] + b0v, acc[mt][nt][3] + b1v);
                *reinterpret_cast<float2*>(C + (size_t)r0 * N + col) = v0;
                *reinterpret_cast<float2*>(C + (size_t)r1 * N + col) = v1;
            }
        }
    }
}

// ---------------- persistent fp16 encoder: 128 blocks (64/dir), 8 dims each ----------------
#define E_WH_B (32 * 520 * 2)
#define E_HS_B (32 * 520 * 2)
#define E_ZS_B (32 * 36 * 4)
#define E_SMEM (E_WH_B + E_HS_B + E_ZS_B)

__global__ __launch_bounds__(256) void k_encoder(const float* __restrict__ Whf,
                                                 const float* __restrict__ Whb)
{
    extern __shared__ char esm[];
    __half (*WhS)[520] = (__half(*)[520])esm;
    __half (*hS)[520]  = (__half(*)[520])(esm + E_WH_B);
    float  (*zS)[36]   = (float(*)[36])(esm + E_WH_B + E_HS_B);

    int dir = blockIdx.x >> 6, chunk = blockIdx.x & 63, d0 = chunk << 3;
    const float* Wh = dir ? Whb : Whf;
    const float* Z  = dir ? g_Zb : g_Zf;
    int tid = threadIdx.x, lane = tid & 31, warp = tid >> 5;
    int gid = lane >> 2, tig = lane & 3;
    int mrow = (warp >> 2) << 4, ncol = (warp & 3) << 3;

    for (int idx = tid; idx < 32 * 512; idx += 256) {
        int j = idx >> 9, k = idx & 511;
        WhS[j][k] = __float2half(Wh[(size_t)k * G4U + (j >> 3) * UU + d0 + (j & 7)]);
    }

    int ub = tid >> 3, ud = tid & 7;
    float cst = 0.f;

    for (int s = 0; s < TT; s++) {
        int t = dir ? (TT - 1 - s) : s;
        size_t zrow = (size_t)(t * BB + ub) * G4U + d0 + ud;
        float zv0 = Z[zrow];
        float zv1 = Z[zrow + UU];
        float zv2 = Z[zrow + 2 * UU];
        float zv3 = Z[zrow + 3 * UU];
        if (s) {
            bar_fast(g_ectr[dir], &g_ego2[dir], s, chunk & 7, chunk == 0);
            int tp = dir ? (t + 1) : (t - 1);
#pragma unroll
            for (int i = tid; i < 32 * 64; i += 256) {
                int b = i >> 6, k8 = (i & 63) << 3;
                uint4 v = *reinterpret_cast<const uint4*>(
                    &g_aH[(size_t)(tp * BB + b) * G2U + dir * UU + k8]);
                *reinterpret_cast<uint4*>(&hS[b][k8]) = v;
            }
            __syncthreads();
            float ac0[4] = {}, ac1[4] = {};
#pragma unroll 8
            for (int ks = 0; ks < 256; ks += 16) {
                int ks2 = ks + 256;
                uint32_t b0 = lds32(&WhS[ncol + gid][ks + 2 * tig]);
                uint32_t b1 = lds32(&WhS[ncol + gid][ks + 2 * tig + 8]);
                uint32_t a0 = lds32(&hS[mrow + gid    ][ks + 2 * tig]);
                uint32_t a1 = lds32(&hS[mrow + gid + 8][ks + 2 * tig]);
                uint32_t a2 = lds32(&hS[mrow + gid    ][ks + 2 * tig + 8]);
                uint32_t a3 = lds32(&hS[mrow + gid + 8][ks + 2 * tig + 8]);
                mma16h(ac0, a0, a1, a2, a3, b0, b1);
                uint32_t c0 = lds32(&WhS[ncol + gid][ks2 + 2 * tig]);
                uint32_t c1 = lds32(&WhS[ncol + gid][ks2 + 2 * tig + 8]);
                uint32_t d0r = lds32(&hS[mrow + gid    ][ks2 + 2 * tig]);
                uint32_t d1r = lds32(&hS[mrow + gid + 8][ks2 + 2 * tig]);
                uint32_t d2r = lds32(&hS[mrow + gid    ][ks2 + 2 * tig + 8]);
                uint32_t d3r = lds32(&hS[mrow + gid + 8][ks2 + 2 * tig + 8]);
                mma16h(ac1, d0r, d1r, d2r, d3r, c0, c1);
            }
            zS[mrow + gid    ][ncol + 2 * tig    ] = ac0[0] + ac1[0];
            zS[mrow + gid    ][ncol + 2 * tig + 1] = ac0[1] + ac1[1];
            zS[mrow + gid + 8][ncol + 2 * tig    ] = ac0[2] + ac1[2];
            zS[mrow + gid + 8][ncol + 2 * tig + 1] = ac0[3] + ac1[3];
            __syncthreads();
        }
        {
            float zi = zv0, zf = zv1, zg = zv2, zo = zv3;
            if (s) {
                zi += zS[ub][ud]; zf += zS[ub][8 + ud];
                zg += zS[ub][16 + ud]; zo += zS[ub][24 + ud];
            }
            float ct = sigf(zf) * cst + sigf(zi) * tanh_fast(zg);
            float h  = sigf(zo) * tanh_fast(ct);
            cst = ct;
            size_t oi = (size_t)(t * BB + ub) * G2U + dir * UU + d0 + ud;
            g_a[oi]  = h;
            g_aH[oi] = __float2half(h);
        }
    }
    __syncthreads();
    if (tid == 0) {
        __threadfence();
        if (atomicAdd(&g_efin[dir], 1) == 63) {
            for (int i = 0; i < 64; i++) g_ectr[dir][i] = 0;
            g_ego2[dir] = 0;
            g_efin[dir] = 0;
        }
    }
}

// ---------------- aW1 = a @ W1[:1024] + b1 -> half, pitch 12 ----------------
__global__ __launch_bounds__(128) void k_aw1(const float* __restrict__ W1,
                                             const float* __restrict__ b1)
{
    __shared__ float red[128][10];
    int r = blockIdx.x;
    int tid = threadIdx.x;
    float acc[10];
#pragma unroll
    for (int j = 0; j < 10; j++) acc[j] = 0.f;
    for (int k = tid; k < G2U; k += 128) {
        float av = g_a[(size_t)r * G2U + k];
#pragma unroll
        for (int j = 0; j < 10; j++) acc[j] += av * W1[(size_t)k * 10 + j];
    }
#pragma unroll
    for (int j = 0; j < 10; j++) red[tid][j] = acc[j];
    __syncthreads();
    for (int s = 64; s > 0; s >>= 1) {
        if (tid < s)
#pragma unroll
            for (int j = 0; j < 10; j++) red[tid][j] += red[tid + s][j];
        __syncthreads();
    }
    if (tid < 12)
        g_aW1H[(size_t)r * 12 + tid] = __float2half((tid < 10) ? (red[0][tid] + b1[tid]) : 0.f);
}

// ---------------- fused decoder + logits GEMM (exp epilogue) ----------------
#define D_WH_OFF  0
#define D_WH_B    (32 * 520 * 2)
#define D_HS_OFF  (D_WH_OFF + D_WH_B)
#define D_HS_B    (32 * 520 * 2)
#define D_AW_OFF  (D_HS_OFF + D_HS_B)
#define D_AW_B    (2048 * 12 * 2)
#define D_W1_OFF  (D_AW_OFF + D_AW_B)
#define D_W1_B    (16 * 520 * 2)
#define D_ZS_OFF  (D_W1_OFF + D_W1_B)
#define D_ZS_B    (32 * 36 * 4)
#define D_SC_OFF  (D_ZS_OFF + D_ZS_B)
#define D_SC_B    (32 * 64 * 4)
#define D_HW_OFF  (D_SC_OFF + D_SC_B)
#define D_HW_B    (32 * 16 * 4)
#define D_CX_OFF  (D_HW_OFF + D_HW_B)
#define D_CX_B    (32 * 32 * 4)
#define D_HP_OFF  (D_CX_OFF + D_CX_B)
#define D_HP_B    (8 * 32 * 16 * 4)
#define D_SMEM    (D_HP_OFF + D_HP_B)
#define G_SRS_OFF (3 * 2 * 128 * 40 * 2)   // 61440, after f16 gemm buffers (< D_SMEM)

__device__ void gemm_tile(char* fsm, const float* __restrict__ bias,
                          float* __restrict__ C, int m0, int n0)
{
    __half (*As)[128][40] = (__half(*)[128][40])fsm;
    __half (*Bs)[128][40] = (__half(*)[128][40])(fsm + 3 * 128 * 40 * 2);
    float* srs = (float*)(fsm + G_SRS_OFF);
    const __half* A  = g_HdH;
    const __half* Bt = g_WoH;
    const int K = DD;
    int tid = threadIdx.x, lane = tid & 31, warp = tid >> 5;
    int gid = lane >> 2, tig = lane & 3;
    int wm = warp & 3, wn = warp >> 2;
    float acc[2][8][4] = {};

    if (tid < 128) srs[tid] = 0.f;

    auto issue = [&](int kt) {
        int st = kt % 3;
        int k0 = kt << 5;
#pragma unroll
        for (int i = 0; i < 2; i++) {
            int idx = tid + (i << 8);
            int r = idx >> 2, c = (idx & 3) << 3;
            uint32_t d = (uint32_t)__cvta_generic_to_shared(&As[st][r][c]);
            const __half* s = A + (size_t)(m0 + r) * K + k0 + c;
            asm volatile("cp.async.cg.shared.global [%0], [%1], 16;\n" :: "r"(d), "l"(s));
        }
#pragma unroll
        for (int i = 0; i < 2; i++) {
            int idx = tid + (i << 8);
            int r = idx >> 2, c = (idx & 3) << 3;
            uint32_t d = (uint32_t)__cvta_generic_to_shared(&Bs[st][r][c]);
            const __half* s = Bt + (size_t)(n0 + r) * K + k0 + c;
            asm volatile("cp.async.cg.shared.global [%0], [%1], 16;\n" :: "r"(d), "l"(s));
        }
        asm volatile("cp.async.commit_group;\n");
    };

    issue(0); issue(1);
#pragma unroll 1
    for (int kt = 0; kt < 16; kt++) {
        if (kt + 2 < 16)      { issue(kt + 2); asm volatile("cp.async.wait_group 2;\n"); }
        else if (kt + 1 < 16) { asm volatile("cp.async.wait_group 1;\n"); }
        else                  { asm volatile("cp.async.wait_group 0;\n"); }
        __syncthreads();
        int st = kt % 3;
#pragma unroll
        for (int ks = 0; ks < 32; ks += 16) {
            uint32_t af[2][4];
#pragma unroll
            for (int mt = 0; mt < 2; mt++) {
                int rb = (wm << 5) + (mt << 4);
                af[mt][0] = *(const uint32_t*)&As[st][rb + gid    ][ks + 2 * tig];
                af[mt][1] = *(const uint32_t*)&As[st][rb + gid + 8][ks + 2 * tig];
                af[mt][2] = *(const uint32_t*)&As[st][rb + gid    ][ks + 2 * tig + 8];
                af[mt][3] = *(const uint32_t*)&As[st][rb + gid + 8][ks + 2 * tig + 8];
            }
#pragma unroll
            for (int nt = 0; nt < 8; nt++) {
                int n = (wn << 6) + (nt << 3) + gid;
                uint32_t b0 = *(const uint32_t*)&Bs[st][n][ks + 2 * tig];
                uint32_t b1 = *(const uint32_t*)&Bs[st][n][ks + 2 * tig + 8];
#pragma unroll
                for (int mt = 0; mt < 2; mt++)
                    mma16h(acc[mt][nt], af[mt][0], af[mt][1], af[mt][2], af[mt][3], b0, b1);
            }
        }
        __syncthreads();
    }
    float rsum[2][2] = {};
#pragma unroll
    for (int mt = 0; mt < 2; mt++) {
#pragma unroll
        for (int nt = 0; nt < 8; nt++) {
            int col = n0 + (wn << 6) + (nt << 3) + (tig << 1);
            float b0v = bias[col], b1v = bias[col + 1];
            int r0 = m0 + (wm << 5) + (mt << 4) + gid;
            int r1 = r0 + 8;
            int or0 = (r0 & 31) * TT + (r0 >> 5);
            int or1 = (r1 & 31) * TT + (r1 >> 5);
            float e0 = __expf(acc[mt][nt][0] + b0v);
            float e1 = __expf(acc[mt][nt][1] + b1v);
            float e2 = __expf(acc[mt][nt][2] + b0v);
            float e3 = __expf(acc[mt][nt][3] + b1v);
            rsum[mt][0] += e0 + e1;
            rsum[mt][1] += e2 + e3;
            *reinterpret_cast<float2*>(C + (size_t)or0 * VV + col) = make_float2(e0, e1);
            *reinterpret_cast<float2*>(C + (size_t)or1 * VV + col) = make_float2(e2, e3);
        }
    }
#pragma unroll
    for (int mt = 0; mt < 2; mt++) {
        int lr = (wm << 5) + (mt << 4) + gid;
        atomicAdd(&srs[lr],     rsum[mt][0]);
        atomicAdd(&srs[lr + 8], rsum[mt][1]);
    }
    __syncthreads();
    if (tid < 128) {
        int r = m0 + tid;
        int orr = (r & 31) * TT + (r >> 5);
        atomicAdd(&g_rowsum[orr], srs[tid]);
    }
    __syncthreads();
}

__global__ __launch_bounds__(256) void k_dec_gemm(
    const float* __restrict__ W2, const float* __restrict__ b2,
    const float* __restrict__ Whd, const float* __restrict__ bd,
    const float* __restrict__ bo, float* __restrict__ out)
{
    extern __shared__ char dsm[];
    __shared__ int s_tile;
    int tid = threadIdx.x;

    if (blockIdx.x < 64) {
        // ---------------- decoder role ----------------
        __half (*WhS)[520]  = (__half(*)[520])(dsm + D_WH_OFF);
        __half (*hS)[520]   = (__half(*)[520])(dsm + D_HS_OFF);
        __half* aW1s        = (__half*)(dsm + D_AW_OFF);
        __half* W1TS        = (__half*)(dsm + D_W1_OFF);     // [16][520], rows 10-15 zero
        float  (*zS)[36]    = (float(*)[36])(dsm + D_ZS_OFF);
        float  (*scS)[64]   = (float(*)[64])(dsm + D_SC_OFF);
        float  (*hW1s)[16]  = (float(*)[16])(dsm + D_HW_OFF);
        float  (*ctxS)[32]  = (float(*)[32])(dsm + D_CX_OFF);
        float*  hp          = (float*)(dsm + D_HP_OFF);      // [8][32][16]

        int chunk = blockIdx.x, d0 = chunk << 3;
        int lane = tid & 31, warp = tid >> 5;
        int gid = lane >> 2, tig = lane & 3;
        int mrow = (warp >> 2) << 4, ncol = (warp & 3) << 3;

        for (int idx = tid; idx < 32 * 512; idx += 256) {
            int j = idx >> 9, k = idx & 511;
            WhS[j][k] = __float2half(Whd[(size_t)k * G4U + (j >> 3) * DD + d0 + (j & 7)]);
        }
        for (int i = tid; i < D_AW_B / 16; i += 256)
            reinterpret_cast<uint4*>(aW1s)[i] = reinterpret_cast<const uint4*>(g_aW1H)[i];
        for (int idx = tid; idx < 16 * 512; idx += 256) {
            int j = idx >> 9, k = idx & 511;
            W1TS[j * 520 + k] = (j < 10) ? g_W1TH[j * 512 + k] : __float2half(0.f);
        }

        float w2r[10];
#pragma unroll
        for (int j = 0; j < 10; j++) w2r[j] = W2[j];
        float b2s = b2[0];

        int cb = tid >> 3, cq = tid & 7, cj4 = cq >> 1, csh = cq & 1;
        const __half* ctx_base = g_aWxdH + (size_t)cb * G4U + chunk * 32 + cj4 * 8;

        int ub = tid >> 3, ud = tid & 7;
        float cst = 0.f;
        float bdv[4];
#pragma unroll
        for (int gg = 0; gg < 4; gg++) bdv[gg] = bd[gg * DD + d0 + ud];

        __syncthreads();

        for (int t = 0; t < TT; t++) {
            if (t) {
                bar_fast(g_dctr, &g_dgo2, t, chunk & 7, chunk == 0);
#pragma unroll
                for (int i = tid; i < 32 * 64; i += 256) {
                    int b = i >> 6, k8 = (i & 63) << 3;
                    uint4 v = *reinterpret_cast<const uint4*>(
                        &g_HdH[(size_t)((t - 1) * BB + b) * DD + k8]);
                    *reinterpret_cast<uint4*>(&hS[b][k8]) = v;
                }
                __syncthreads();
                // ---- fused mma phase: hW1 (k-split over 8 warps) + z-mma ----
                {
                    int k0 = warp << 6;
                    float h00[4] = {}, h01[4] = {}, h10[4] = {}, h11[4] = {};
#pragma unroll
                    for (int ks = 0; ks < 64; ks += 16) {
                        int kk = k0 + ks;
                        uint32_t b0 = lds32(&W1TS[gid * 520 + kk + 2 * tig]);
                        uint32_t b1 = lds32(&W1TS[gid * 520 + kk + 2 * tig + 8]);
                        uint32_t c0 = lds32(&W1TS[(8 + gid) * 520 + kk + 2 * tig]);
                        uint32_t c1 = lds32(&W1TS[(8 + gid) * 520 + kk + 2 * tig + 8]);
                        uint32_t a0 = lds32(&hS[gid    ][kk + 2 * tig]);
                        uint32_t a1 = lds32(&hS[gid + 8][kk + 2 * tig]);
                        uint32_t a2 = lds32(&hS[gid    ][kk + 2 * tig + 8]);
                        uint32_t a3 = lds32(&hS[gid + 8][kk + 2 * tig + 8]);
                        mma16h(h00, a0, a1, a2, a3, b0, b1);
                        mma16h(h01, a0, a1, a2, a3, c0, c1);
                        uint32_t u0 = lds32(&hS[16 + gid][kk + 2 * tig]);
                        uint32_t u1 = lds32(&hS[24 + gid][kk + 2 * tig]);
                        uint32_t u2 = lds32(&hS[16 + gid][kk + 2 * tig + 8]);
                        uint32_t u3 = lds32(&hS[24 + gid][kk + 2 * tig + 8]);
                        mma16h(h10, u0, u1, u2, u3, b0, b1);
                        mma16h(h11, u0, u1, u2, u3, c0, c1);
                    }
                    float* hpw = hp + (warp << 9);
                    hpw[(gid     ) * 16 + 2 * tig    ] = h00[0];
                    hpw[(gid     ) * 16 + 2 * tig + 1] = h00[1];
                    hpw[(gid +  8) * 16 + 2 * tig    ] = h00[2];
                    hpw[(gid +  8) * 16 + 2 * tig + 1] = h00[3];
                    hpw[(gid     ) * 16 + 2 * tig + 8] = h01[0];
                    hpw[(gid     ) * 16 + 2 * tig + 9] = h01[1];
                    hpw[(gid +  8) * 16 + 2 * tig + 8] = h01[2];
                    hpw[(gid +  8) * 16 + 2 * tig + 9] = h01[3];
                    hpw[(gid + 16) * 16 + 2 * tig    ] = h10[0];
                    hpw[(gid + 16) * 16 + 2 * tig + 1] = h10[1];
                    hpw[(gid + 24) * 16 + 2 * tig    ] = h10[2];
                    hpw[(gid + 24) * 16 + 2 * tig + 1] = h10[3];
                    hpw[(gid + 16) * 16 + 2 * tig + 8] = h11[0];
                    hpw[(gid + 16) * 16 + 2 * tig + 9] = h11[1];
                    hpw[(gid + 24) * 16 + 2 * tig + 8] = h11[2];
                    hpw[(gid + 24) * 16 + 2 * tig + 9] = h11[3];
                }
                {
                    float ac0[4] = {}, ac1[4] = {};
#pragma unroll 8
                    for (int ks = 0; ks < 256; ks += 16) {
                        int ks2 = ks + 256;
                        uint32_t b0 = lds32(&WhS[ncol + gid][ks + 2 * tig]);
                        uint32_t b1 = lds32(&WhS[ncol + gid][ks + 2 * tig + 8]);
                        uint32_t a0 = lds32(&hS[mrow + gid    ][ks + 2 * tig]);
                        uint32_t a1 = lds32(&hS[mrow + gid + 8][ks + 2 * tig]);
                        uint32_t a2 = lds32(&hS[mrow + gid    ][ks + 2 * tig + 8]);
                        uint32_t a3 = lds32(&hS[mrow + gid + 8][ks + 2 * tig + 8]);
                        mma16h(ac0, a0, a1, a2, a3, b0, b1);
                        uint32_t c0 = lds32(&WhS[ncol + gid][ks2 + 2 * tig]);
                        uint32_t c1 = lds32(&WhS[ncol + gid][ks2 + 2 * tig + 8]);
                        uint32_t e0 = lds32(&hS[mrow + gid    ][ks2 + 2 * tig]);
                        uint32_t e1 = lds32(&hS[mrow + gid + 8][ks2 + 2 * tig]);
                        uint32_t e2 = lds32(&hS[mrow + gid    ][ks2 + 2 * tig + 8]);
                        uint32_t e3 = lds32(&hS[mrow + gid + 8][ks2 + 2 * tig + 8]);
                        mma16h(ac1, e0, e1, e2, e3, c0, c1);
                    }
                    zS[mrow + gid    ][ncol + 2 * tig    ] = ac0[0] + ac1[0];
                    zS[mrow + gid    ][ncol + 2 * tig + 1] = ac0[1] + ac1[1];
                    zS[mrow + gid + 8][ncol + 2 * tig    ] = ac0[2] + ac1[2];
                    zS[mrow + gid + 8][ncol + 2 * tig + 1] = ac0[3] + ac1[3];
                }
                __syncthreads();
                // reduce hW1 partials
                for (int p = tid; p < 512; p += 256) {
                    float s = hp[p] + hp[512 + p] + hp[1024 + p] + hp[1536 + p]
                            + hp[2048 + p] + hp[2560 + p] + hp[3072 + p] + hp[3584 + p];
                    hW1s[p >> 4][p & 15] = s;
                }
            } else {
                for (int p = tid; p < 512; p += 256) hW1s[p >> 4][p & 15] = 0.f;
            }
            __syncthreads();
            // attention energies
            for (int p = tid; p < 2048; p += 256) {
                int b = p & 31;
                const __half* aw = &aW1s[p * 12];
                float v = b2s;
#pragma unroll
                for (int j = 0; j < 10; j++)
                    v += tanh_fast(__half2float(aw[j]) + hW1s[b][j]) * w2r[j];
                scS[b][p >> 5] = fmaxf(v, 0.f);
            }
            __syncthreads();
            // softmax over s per row (8 lanes per row)
            {
                int b = tid >> 3, g8 = tid & 7;
                float vv[8];
                float m = -1e30f;
#pragma unroll
                for (int q = 0; q < 8; q++) { vv[q] = scS[b][g8 * 8 + q]; m = fmaxf(m, vv[q]); }
#pragma unroll
                for (int o = 1; o < 8; o <<= 1) m = fmaxf(m, __shfl_xor_sync(0xffffffffu, m, o));
                float sm = 0.f;
#pragma unroll
                for (int q = 0; q < 8; q++) { vv[q] = __expf(vv[q] - m); sm += vv[q]; }
#pragma unroll
                for (int o = 1; o < 8; o <<= 1) sm += __shfl_xor_sync(0xffffffffu, sm, o);
                float inv = 1.f / sm;
#pragma unroll
                for (int q = 0; q < 8; q++) scS[b][g8 * 8 + q] = vv[q] * inv;
            }
            __syncthreads();
            // ctx
            float ca[8] = {};
            {
                int s0 = csh << 5;
#pragma unroll 8
                for (int s5 = s0; s5 < s0 + 32; s5++) {
                    float sc = scS[cb][s5];
                    uint4 v = *reinterpret_cast<const uint4*>(ctx_base + (size_t)s5 * BB * G4U);
                    float2 f0 = __half22float2(*(const __half2*)&v.x);
                    float2 f1 = __half22float2(*(const __half2*)&v.y);
                    float2 f2 = __half22float2(*(const __half2*)&v.z);
                    float2 f3 = __half22float2(*(const __half2*)&v.w);
                    ca[0] += sc * f0.x; ca[1] += sc * f0.y;
                    ca[2] += sc * f1.x; ca[3] += sc * f1.y;
                    ca[4] += sc * f2.x; ca[5] += sc * f2.y;
                    ca[6] += sc * f3.x; ca[7] += sc * f3.y;
                }
            }
#pragma unroll
            for (int q = 0; q < 8; q++) ca[q] += __shfl_xor_sync(0xffffffffu, ca[q], 1);
            if (csh == 0) {
#pragma unroll
                for (int q = 0; q < 8; q++) ctxS[cb][cj4 * 8 + q] = ca[q];
            }
            __syncthreads();
            // cell update
            {
                float z[4];
#pragma unroll
                for (int gg = 0; gg < 4; gg++) {
                    float zz = ctxS[ub][gg * 8 + ud] + bdv[gg];
                    if (t) zz += zS[ub][gg * 8 + ud];
                    z[gg] = zz;
                }
                float ct = sigf(z[1]) * cst + sigf(z[0]) * tanh_fast(z[2]);
                float h  = sigf(z[3]) * tanh_fast(ct);
                cst = ct;
                g_HdH[(size_t)(t * BB + ub) * DD + d0 + ud] = __float2half(h);
            }
        }
        __syncthreads();
        if (tid == 0) red_rel(&g_dall);
        __syncthreads();
    }

    // ---------------- gemm role (all blocks; decoder blocks join after finishing) ----------------
    for (;;) {
        if (tid == 0) s_tile = atomicAdd(&g_tile, 1);
        __syncthreads();
        int tile = s_tile;
        __syncthreads();
        if (tile >= NTILES) break;
        int mt5 = tile / 250, nt5 = tile % 250;
        __syncthreads();
        if (tid == 0) {
            if (mt5 >= 15) { while (ld_acq(&g_dall) < 64) { } }
            else           { while (ld_acq(&g_dgo2) < (mt5 << 2) + 4) { } }
        }
        __syncthreads();
        gemm_tile(dsm, bo, out, mt5 << 7, nt5 << 7);
    }
    if (tid == 0) {
        if (atomicAdd(&g_gfin, 1) == 147) {
            g_tile = 0;
            g_gfin = 0;
            g_dall = 0;
            g_dgo2 = 0;
            for (int i = 0; i < 64; i++) g_dctr[i] = 0;
        }
    }
}

// ---------------- normalize: out = exp / rowsum ----------------
__global__ void k_norm(float* __restrict__ out) {
    int r = blockIdx.x;
    float inv = 1.f / g_rowsum[r];
    float4* p = reinterpret_cast<float4*>(out + (size_t)r * VV);
    for (int i = threadIdx.x; i < VV / 4; i += 256) {
        float4 v = p[i];
        v.x *= inv; v.y *= inv; v.z *= inv; v.w *= inv;
        p[i] = v;
    }
}

// ---------------- host driver ----------------
extern "C" void kernel_launch(void* const* d_in, const int* in_sizes, int n_in,
                              void* d_out, int out_size)
{
    (void)in_sizes; (void)n_in; (void)out_size;
    const int*   x   = (const int*)  d_in[0];
    const float* emb = (const float*)d_in[1];
    const float* Wxf = (const float*)d_in[2];
    const float* Whf = (const float*)d_in[3];
    const float* bf  = (const float*)d_in[4];
    const float* Wxb = (const float*)d_in[5];
    const float* Whb = (const float*)d_in[6];
    const float* bbv = (const float*)d_in[7];
    const float* W1  = (const float*)d_in[8];
    const float* b1  = (const float*)d_in[9];
    const float* W2  = (const float*)d_in[10];
    const float* b2  = (const float*)d_in[11];
    const float* Wxd = (const float*)d_in[12];
    const float* Whd = (const float*)d_in[13];
    const float* bd  = (const float*)d_in[14];
    const float* Wo  = (const float*)d_in[15];
    const float* bo  = (const float*)d_in[16];
    float* out = (float*)d_out;

    float *p_xe, *p_Zf, *p_Zb, *p_a;
    __half *p_aWxdH;
    cudaGetSymbolAddress((void**)&p_xe,    g_xe);
    cudaGetSymbolAddress((void**)&p_Zf,    g_Zf);
    cudaGetSymbolAddress((void**)&p_Zb,    g_Zb);
    cudaGetSymbolAddress((void**)&p_a,     g_a);
    cudaGetSymbolAddress((void**)&p_aWxdH, g_aWxdH);

    cudaFuncSetAttribute(k_gemm,     cudaFuncAttributeMaxDynamicSharedMemorySize, 75776);
    cudaFuncSetAttribute(k_encoder,  cudaFuncAttributeMaxDynamicSharedMemorySize, E_SMEM);
    cudaFuncSetAttribute(k_dec_gemm, cudaFuncAttributeMaxDynamicSharedMemorySize, D_SMEM);

    k_embed<<<NTOK, 64>>>(x, emb);
    k_cvt_wo<<<dim3(VV / 32, DD / 32), dim3(32, 8)>>>(Wo);
    k_gemm<<<dim3(G4U / 128, NTOK / 128), 256, 75776>>>(p_xe, Wxf, bf,  p_Zf, nullptr, NTOK, G4U, EE);
    k_gemm<<<dim3(G4U / 128, NTOK / 128), 256, 75776>>>(p_xe, Wxb, bbv, p_Zb, nullptr, NTOK, G4U, EE);
    k_encoder<<<128, 256, E_SMEM>>>(Whf, Whb);
    k_gemm<<<dim3(G4U / 128, NTOK / 128), 256, 75776>>>(p_a, Wxd, nullptr, nullptr, p_aWxdH, NTOK, G4U, G2U);
    k_aw1<<<NTOK, 128>>>(W1, b1);
    k_w1t<<<10, 512>>>(W1);
    k_dec_gemm<<<148, 256, D_SMEM>>>(W2, b2, Whd, bd, bo, out);
    k_norm<<<NTOK, 256>>>(out);
}

// round 12
// speedup vs baseline: 1.1272x; 1.1272x over previous
#include <cuda_runtime.h>
#include <cuda_fp16.h>
#include <cstdint>

#define BB   32
#define TT   64
#define EE   256
#define UU   512
#define DD   512
#define VV   32000
#define NTOK 2048
#define G4U  2048
#define G2U  1024
#define NTILES 4000          // (2048/128) * (32000/128)

// ---------------- scratch ----------------
__device__ float  g_xe   [NTOK * EE];
__device__ float  g_Zf   [NTOK * G4U];
__device__ float  g_Zb   [NTOK * G4U];
__device__ float  g_a    [NTOK * G2U];
__device__ __half g_aH   [NTOK * G2U];
__device__ __half g_aW1H [NTOK * 12];
__device__ __half g_aWxdH[NTOK * G4U];
__device__ __half g_HdH  [NTOK * DD];
__device__ __half g_WoH  [VV * DD];
__device__ __half g_W1TH [10 * 512];
__device__ float  g_rowsum[NTOK];
// barrier state: 8 spread counters (128B apart) per barrier
__device__ int    g_ectr[2][256];
__device__ int    g_efin[2];
__device__ int    g_dctr[256];
__device__ int    g_dfin;
__device__ int    g_dprog;   // decoder step completion counter (64 per step)
__device__ int    g_tile;    // gemm tile dispenser
__device__ int    g_gfin;    // gemm role finish counter

__device__ __forceinline__ float sigf(float x) { return 1.f / (1.f + __expf(-x)); }
__device__ __forceinline__ float tanh_fast(float x) {
    float r; asm("tanh.approx.f32 %0, %1;" : "=f"(r) : "f"(x)); return r;
}
__device__ __forceinline__ int ld_acq(const int* p) {
    int v; asm volatile("ld.acquire.gpu.global.b32 %0, [%1];" : "=r"(v) : "l"(p) : "memory");
    return v;
}
__device__ __forceinline__ void red_rel(int* p) {
    asm volatile("red.release.gpu.global.add.s32 [%0], 1;" :: "l"(p) : "memory");
}

// spread-counter barrier: arrival on ctr[grp*32]; release when sum over 8 counters == step*64.
// No leader, no second hop; arrive is release, polls are acquire.
__device__ __forceinline__ void bar_spread(int* ctr, int step, int grp) {
    __syncthreads();
    if (threadIdx.x == 0) {
        red_rel(&ctr[grp * 32]);
        int need = step * 64;
        int s;
        do {
            s = 0;
#pragma unroll
            for (int i = 0; i < 8; i++) s += ld_acq(&ctr[i * 32]);
        } while (s < need);
    }
    __syncthreads();
}

__device__ __forceinline__ void mma8(float* c, uint32_t a0, uint32_t a1, uint32_t a2, uint32_t a3,
                                     uint32_t b0, uint32_t b1) {
    asm volatile(
        "mma.sync.aligned.m16n8k8.row.col.f32.tf32.tf32.f32 "
        "{%0,%1,%2,%3}, {%4,%5,%6,%7}, {%8,%9}, {%0,%1,%2,%3};\n"
        : "+f"(c[0]), "+f"(c[1]), "+f"(c[2]), "+f"(c[3])
        : "r"(a0), "r"(a1), "r"(a2), "r"(a3), "r"(b0), "r"(b1));
}
__device__ __forceinline__ void mma16h(float* c, uint32_t a0, uint32_t a1, uint32_t a2, uint32_t a3,
                                       uint32_t b0, uint32_t b1) {
    asm volatile(
        "mma.sync.aligned.m16n8k16.row.col.f32.f16.f16.f32 "
        "{%0,%1,%2,%3}, {%4,%5,%6,%7}, {%8,%9}, {%0,%1,%2,%3};\n"
        : "+f"(c[0]), "+f"(c[1]), "+f"(c[2]), "+f"(c[3])
        : "r"(a0), "r"(a1), "r"(a2), "r"(a3), "r"(b0), "r"(b1));
}
__device__ __forceinline__ uint32_t lds32(const __half* p) { return *(const uint32_t*)p; }

// ---------------- embedding gather + rowsum zero ----------------
__global__ void k_embed(const int* __restrict__ x, const float* __restrict__ emb) {
    int row = blockIdx.x;
    int t = row >> 5, b = row & 31;
    int tok = x[b * TT + t];
    const float4* src = reinterpret_cast<const float4*>(emb + (size_t)tok * EE);
    float4* dst = reinterpret_cast<float4*>(g_xe + (size_t)row * EE);
    dst[threadIdx.x] = src[threadIdx.x];
    if (threadIdx.x == 0) g_rowsum[row] = 0.f;
}

// ---------------- Wo convert + transpose ----------------
__global__ void k_cvt_wo(const float* __restrict__ Wo) {
    __shared__ float t[32][33];
    int n0 = blockIdx.x << 5, k0 = blockIdx.y << 5;
    for (int i = threadIdx.y; i < 32; i += 8)
        t[i][threadIdx.x] = Wo[(size_t)(k0 + i) * VV + n0 + threadIdx.x];
    __syncthreads();
    for (int i = threadIdx.y; i < 32; i += 8)
        g_WoH[(size_t)(n0 + i) * DD + k0 + threadIdx.x] = __float2half(t[threadIdx.x][i]);
}

// ---------------- W1 decoder-half transpose ----------------
__global__ void k_w1t(const float* __restrict__ W1) {
    int j = blockIdx.x;
    for (int k = threadIdx.x; k < 512; k += blockDim.x)
        g_W1TH[j * 512 + k] = __float2half(W1[(size_t)(G2U + k) * 10 + j]);
}

// ---------------- tf32 GEMM (double-buffered); Ch!=null -> permuted half output ----------------
__global__ __launch_bounds__(256) void k_gemm(
    const float* __restrict__ A, const float* __restrict__ B,
    const float* __restrict__ bias, float* __restrict__ C, __half* __restrict__ Ch,
    int M, int N, int K)
{
    extern __shared__ char gsm[];
    uint32_t (*As)[128][40] = (uint32_t(*)[128][40])gsm;
    uint32_t (*Bs)[32][136] = (uint32_t(*)[32][136])(gsm + 2 * 128 * 40 * 4);
    int tid = threadIdx.x, lane = tid & 31, warp = tid >> 5;
    int gid = lane >> 2, tig = lane & 3;
    int wm = warp & 3, wn = warp >> 2;
    int m0 = blockIdx.y << 7, n0 = blockIdx.x << 7;
    int ntile = K >> 5;
    float acc[2][8][4] = {};

    auto issue = [&](int kt) {
        int st = kt & 1;
        int k0 = kt << 5;
#pragma unroll
        for (int i = 0; i < 4; i++) {
            int idx = tid + (i << 8);
            int r = idx >> 3, c4 = (idx & 7) << 2;
            uint32_t d = (uint32_t)__cvta_generic_to_shared(&As[st][r][c4]);
            const float* s = A + (size_t)(m0 + r) * K + k0 + c4;
            asm volatile("cp.async.cg.shared.global [%0], [%1], 16;\n" :: "r"(d), "l"(s));
        }
#pragma unroll
        for (int i = 0; i < 4; i++) {
            int idx = tid + (i << 8);
            int r = idx >> 5, c4 = (idx & 31) << 2;
            uint32_t d = (uint32_t)__cvta_generic_to_shared(&Bs[st][r][c4]);
            const float* s = B + (size_t)(k0 + r) * N + n0 + c4;
            asm volatile("cp.async.cg.shared.global [%0], [%1], 16;\n" :: "r"(d), "l"(s));
        }
        asm volatile("cp.async.commit_group;\n");
    };

    issue(0);
    for (int kt = 0; kt < ntile; kt++) {
        if (kt + 1 < ntile) { issue(kt + 1); asm volatile("cp.async.wait_group 1;\n"); }
        else                 { asm volatile("cp.async.wait_group 0;\n"); }
        __syncthreads();
        int st = kt & 1;
#pragma unroll
        for (int kk = 0; kk < 32; kk += 8) {
            uint32_t af[2][4];
#pragma unroll
            for (int mt = 0; mt < 2; mt++) {
                int rb = (wm << 5) + (mt << 4);
                af[mt][0] = As[st][rb + gid    ][kk + tig];
                af[mt][1] = As[st][rb + gid + 8][kk + tig];
                af[mt][2] = As[st][rb + gid    ][kk + tig + 4];
                af[mt][3] = As[st][rb + gid + 8][kk + tig + 4];
            }
#pragma unroll
            for (int nt = 0; nt < 8; nt++) {
                uint32_t b0 = Bs[st][kk + tig    ][(wn << 6) + (nt << 3) + gid];
                uint32_t b1 = Bs[st][kk + tig + 4][(wn << 6) + (nt << 3) + gid];
#pragma unroll
                for (int mt = 0; mt < 2; mt++)
                    mma8(acc[mt][nt], af[mt][0], af[mt][1], af[mt][2], af[mt][3], b0, b1);
            }
        }
        __syncthreads();
    }
#pragma unroll
    for (int mt = 0; mt < 2; mt++) {
#pragma unroll
        for (int nt = 0; nt < 8; nt++) {
            int col = n0 + (wn << 6) + (nt << 3) + (tig << 1);
            int r0 = m0 + (wm << 5) + (mt << 4) + gid;
            int r1 = r0 + 8;
            if (Ch) {
                int d = col & 511, gate = col >> 9;
                int nc = ((d >> 3) << 5) + (gate << 3) + (d & 7);
                *reinterpret_cast<__half2*>(Ch + (size_t)r0 * N + nc) =
                    __floats2half2_rn(acc[mt][nt][0], acc[mt][nt][1]);
                *reinterpret_cast<__half2*>(Ch + (size_t)r1 * N + nc) =
                    __floats2half2_rn(acc[mt][nt][2], acc[mt][nt][3]);
            } else {
                float b0v = bias ? bias[col]     : 0.f;
                float b1v = bias ? bias[col + 1] : 0.f;
                float2 v0 = make_float2(acc[mt][nt][0] + b0v, acc[mt][nt][1] + b1v);
                float2 v1 = make_float2(acc[mt][nt][2] + b0v, acc[mt][nt][3] + b1v);
                *reinterpret_cast<float2*>(C + (size_t)r0 * N + col) = v0;
                *reinterpret_cast<float2*>(C + (size_t)r1 * N + col) = v1;
            }
        }
    }
}

// ---------------- persistent fp16 encoder: 128 blocks (64/dir), 8 dims each ----------------
#define E_WH_B (32 * 520 * 2)
#define E_HS_B (32 * 520 * 2)
#define E_ZS_B (32 * 36 * 4)
#define E_SMEM (E_WH_B + E_HS_B + E_ZS_B)

__global__ __launch_bounds__(256) void k_encoder(const float* __restrict__ Whf,
                                                 const float* __restrict__ Whb)
{
    extern __shared__ char esm[];
    __half (*WhS)[520] = (__half(*)[520])esm;
    __half (*hS)[520]  = (__half(*)[520])(esm + E_WH_B);
    float  (*zS)[36]   = (float(*)[36])(esm + E_WH_B + E_HS_B);

    int dir = blockIdx.x >> 6, chunk = blockIdx.x & 63, d0 = chunk << 3;
    const float* Wh = dir ? Whb : Whf;
    const float* Z  = dir ? g_Zb : g_Zf;
    int tid = threadIdx.x, lane = tid & 31, warp = tid >> 5;
    int gid = lane >> 2, tig = lane & 3;
    int mrow = (warp >> 2) << 4, ncol = (warp & 3) << 3;

    for (int idx = tid; idx < 32 * 512; idx += 256) {
        int j = idx >> 9, k = idx & 511;
        WhS[j][k] = __float2half(Wh[(size_t)k * G4U + (j >> 3) * UU + d0 + (j & 7)]);
    }

    int ub = tid >> 3, ud = tid & 7;
    float cst = 0.f;

    for (int s = 0; s < TT; s++) {
        int t = dir ? (TT - 1 - s) : s;
        size_t zrow = (size_t)(t * BB + ub) * G4U + d0 + ud;
        float zv0 = Z[zrow];
        float zv1 = Z[zrow + UU];
        float zv2 = Z[zrow + 2 * UU];
        float zv3 = Z[zrow + 3 * UU];
        if (s) {
            bar_spread(g_ectr[dir], s, chunk & 7);
            int tp = dir ? (t + 1) : (t - 1);
#pragma unroll
            for (int i = tid; i < 32 * 64; i += 256) {
                int b = i >> 6, k8 = (i & 63) << 3;
                uint4 v = *reinterpret_cast<const uint4*>(
                    &g_aH[(size_t)(tp * BB + b) * G2U + dir * UU + k8]);
                *reinterpret_cast<uint4*>(&hS[b][k8]) = v;
            }
            __syncthreads();
            float ac0[4] = {}, ac1[4] = {};
#pragma unroll 8
            for (int ks = 0; ks < 256; ks += 16) {
                int ks2 = ks + 256;
                uint32_t b0 = lds32(&WhS[ncol + gid][ks + 2 * tig]);
                uint32_t b1 = lds32(&WhS[ncol + gid][ks + 2 * tig + 8]);
                uint32_t a0 = lds32(&hS[mrow + gid    ][ks + 2 * tig]);
                uint32_t a1 = lds32(&hS[mrow + gid + 8][ks + 2 * tig]);
                uint32_t a2 = lds32(&hS[mrow + gid    ][ks + 2 * tig + 8]);
                uint32_t a3 = lds32(&hS[mrow + gid + 8][ks + 2 * tig + 8]);
                mma16h(ac0, a0, a1, a2, a3, b0, b1);
                uint32_t c0 = lds32(&WhS[ncol + gid][ks2 + 2 * tig]);
                uint32_t c1 = lds32(&WhS[ncol + gid][ks2 + 2 * tig + 8]);
                uint32_t d0r = lds32(&hS[mrow + gid    ][ks2 + 2 * tig]);
                uint32_t d1r = lds32(&hS[mrow + gid + 8][ks2 + 2 * tig]);
                uint32_t d2r = lds32(&hS[mrow + gid    ][ks2 + 2 * tig + 8]);
                uint32_t d3r = lds32(&hS[mrow + gid + 8][ks2 + 2 * tig + 8]);
                mma16h(ac1, d0r, d1r, d2r, d3r, c0, c1);
            }
            zS[mrow + gid    ][ncol + 2 * tig    ] = ac0[0] + ac1[0];
            zS[mrow + gid    ][ncol + 2 * tig + 1] = ac0[1] + ac1[1];
            zS[mrow + gid + 8][ncol + 2 * tig    ] = ac0[2] + ac1[2];
            zS[mrow + gid + 8][ncol + 2 * tig + 1] = ac0[3] + ac1[3];
            __syncthreads();
        }
        {
            float zi = zv0, zf = zv1, zg = zv2, zo = zv3;
            if (s) {
                zi += zS[ub][ud]; zf += zS[ub][8 + ud];
                zg += zS[ub][16 + ud]; zo += zS[ub][24 + ud];
            }
            float ct = sigf(zf) * cst + sigf(zi) * tanh_fast(zg);
            float h  = sigf(zo) * tanh_fast(ct);
            cst = ct;
            size_t oi = (size_t)(t * BB + ub) * G2U + dir * UU + d0 + ud;
            g_a[oi]  = h;
            g_aH[oi] = __float2half(h);
        }
    }
    __syncthreads();
    if (tid == 0) {
        __threadfence();
        if (atomicAdd(&g_efin[dir], 1) == 63) {
            for (int i = 0; i < 256; i++) g_ectr[dir][i] = 0;
            g_efin[dir] = 0;
        }
    }
}

// ---------------- aW1 = a @ W1[:1024] + b1 -> half, pitch 12 ----------------
__global__ __launch_bounds__(128) void k_aw1(const float* __restrict__ W1,
                                             const float* __restrict__ b1)
{
    __shared__ float red[128][10];
    int r = blockIdx.x;
    int tid = threadIdx.x;
    float acc[10];
#pragma unroll
    for (int j = 0; j < 10; j++) acc[j] = 0.f;
    for (int k = tid; k < G2U; k += 128) {
        float av = g_a[(size_t)r * G2U + k];
#pragma unroll
        for (int j = 0; j < 10; j++) acc[j] += av * W1[(size_t)k * 10 + j];
    }
#pragma unroll
    for (int j = 0; j < 10; j++) red[tid][j] = acc[j];
    __syncthreads();
    for (int s = 64; s > 0; s >>= 1) {
        if (tid < s)
#pragma unroll
            for (int j = 0; j < 10; j++) red[tid][j] += red[tid + s][j];
        __syncthreads();
    }
    if (tid < 12)
        g_aW1H[(size_t)r * 12 + tid] = __float2half((tid < 10) ? (red[0][tid] + b1[tid]) : 0.f);
}

// ---------------- fused decoder + logits GEMM (exp epilogue) ----------------
#define D_WH_OFF  0
#define D_WH_B    (32 * 520 * 2)
#define D_HS_OFF  (D_WH_OFF + D_WH_B)
#define D_HS_B    (32 * 520 * 2)
#define D_AW_OFF  (D_HS_OFF + D_HS_B)
#define D_AW_B    (2048 * 12 * 2)
#define D_W1_OFF  (D_AW_OFF + D_AW_B)
#define D_W1_B    (10 * 520 * 2)
#define D_ZS_OFF  (D_W1_OFF + D_W1_B)
#define D_ZS_B    (32 * 36 * 4)
#define D_SC_OFF  (D_ZS_OFF + D_ZS_B)
#define D_SC_B    (32 * 64 * 4)
#define D_HW_OFF  (D_SC_OFF + D_SC_B)
#define D_HW_B    (32 * 10 * 4)
#define D_CX_OFF  (D_HW_OFF + D_HW_B)
#define D_CX_B    (32 * 32 * 4)
#define D_SMEM    (D_CX_OFF + D_CX_B)
#define G_SRS_OFF (3 * 2 * 128 * 40 * 2)   // 61440, after f16 gemm buffers (< D_SMEM)

__device__ void gemm_tile(char* fsm, const float* __restrict__ bias,
                          float* __restrict__ C, int m0, int n0)
{
    __half (*As)[128][40] = (__half(*)[128][40])fsm;
    __half (*Bs)[128][40] = (__half(*)[128][40])(fsm + 3 * 128 * 40 * 2);
    float* srs = (float*)(fsm + G_SRS_OFF);
    const __half* A  = g_HdH;
    const __half* Bt = g_WoH;
    const int K = DD;
    int tid = threadIdx.x, lane = tid & 31, warp = tid >> 5;
    int gid = lane >> 2, tig = lane & 3;
    int wm = warp & 3, wn = warp >> 2;
    float acc[2][8][4] = {};

    if (tid < 128) srs[tid] = 0.f;

    auto issue = [&](int kt) {
        int st = kt % 3;
        int k0 = kt << 5;
#pragma unroll
        for (int i = 0; i < 2; i++) {
            int idx = tid + (i << 8);
            int r = idx >> 2, c = (idx & 3) << 3;
            uint32_t d = (uint32_t)__cvta_generic_to_shared(&As[st][r][c]);
            const __half* s = A + (size_t)(m0 + r) * K + k0 + c;
            asm volatile("cp.async.cg.shared.global [%0], [%1], 16;\n" :: "r"(d), "l"(s));
        }
#pragma unroll
        for (int i = 0; i < 2; i++) {
            int idx = tid + (i << 8);
            int r = idx >> 2, c = (idx & 3) << 3;
            uint32_t d = (uint32_t)__cvta_generic_to_shared(&Bs[st][r][c]);
            const __half* s = Bt + (size_t)(n0 + r) * K + k0 + c;
            asm volatile("cp.async.cg.shared.global [%0], [%1], 16;\n" :: "r"(d), "l"(s));
        }
        asm volatile("cp.async.commit_group;\n");
    };

    issue(0); issue(1);
#pragma unroll 1
    for (int kt = 0; kt < 16; kt++) {
        if (kt + 2 < 16)      { issue(kt + 2); asm volatile("cp.async.wait_group 2;\n"); }
        else if (kt + 1 < 16) { asm volatile("cp.async.wait_group 1;\n"); }
        else                  { asm volatile("cp.async.wait_group 0;\n"); }
        __syncthreads();
        int st = kt % 3;
#pragma unroll
        for (int ks = 0; ks < 32; ks += 16) {
            uint32_t af[2][4];
#pragma unroll
            for (int mt = 0; mt < 2; mt++) {
                int rb = (wm << 5) + (mt << 4);
                af[mt][0] = *(const uint32_t*)&As[st][rb + gid    ][ks + 2 * tig];
                af[mt][1] = *(const uint32_t*)&As[st][rb + gid + 8][ks + 2 * tig];
                af[mt][2] = *(const uint32_t*)&As[st][rb + gid    ][ks + 2 * tig + 8];
                af[mt][3] = *(const uint32_t*)&As[st][rb + gid + 8][ks + 2 * tig + 8];
            }
#pragma unroll
            for (int nt = 0; nt < 8; nt++) {
                int n = (wn << 6) + (nt << 3) + gid;
                uint32_t b0 = *(const uint32_t*)&Bs[st][n][ks + 2 * tig];
                uint32_t b1 = *(const uint32_t*)&Bs[st][n][ks + 2 * tig + 8];
#pragma unroll
                for (int mt = 0; mt < 2; mt++)
                    mma16h(acc[mt][nt], af[mt][0], af[mt][1], af[mt][2], af[mt][3], b0, b1);
            }
        }
        __syncthreads();
    }
    float rsum[2][2] = {};
#pragma unroll
    for (int mt = 0; mt < 2; mt++) {
#pragma unroll
        for (int nt = 0; nt < 8; nt++) {
            int col = n0 + (wn << 6) + (nt << 3) + (tig << 1);
            float b0v = bias[col], b1v = bias[col + 1];
            int r0 = m0 + (wm << 5) + (mt << 4) + gid;
            int r1 = r0 + 8;
            int or0 = (r0 & 31) * TT + (r0 >> 5);
            int or1 = (r1 & 31) * TT + (r1 >> 5);
            float e0 = __expf(acc[mt][nt][0] + b0v);
            float e1 = __expf(acc[mt][nt][1] + b1v);
            float e2 = __expf(acc[mt][nt][2] + b0v);
            float e3 = __expf(acc[mt][nt][3] + b1v);
            rsum[mt][0] += e0 + e1;
            rsum[mt][1] += e2 + e3;
            *reinterpret_cast<float2*>(C + (size_t)or0 * VV + col) = make_float2(e0, e1);
            *reinterpret_cast<float2*>(C + (size_t)or1 * VV + col) = make_float2(e2, e3);
        }
    }
#pragma unroll
    for (int mt = 0; mt < 2; mt++) {
        int lr = (wm << 5) + (mt << 4) + gid;
        atomicAdd(&srs[lr],     rsum[mt][0]);
        atomicAdd(&srs[lr + 8], rsum[mt][1]);
    }
    __syncthreads();
    if (tid < 128) {
        int r = m0 + tid;
        int orr = (r & 31) * TT + (r >> 5);
        atomicAdd(&g_rowsum[orr], srs[tid]);
    }
    __syncthreads();
}

__global__ __launch_bounds__(256) void k_dec_gemm(
    const float* __restrict__ W2, const float* __restrict__ b2,
    const float* __restrict__ Whd, const float* __restrict__ bd,
    const float* __restrict__ bo, float* __restrict__ out)
{
    extern __shared__ char dsm[];
    __shared__ int s_tile;
    int tid = threadIdx.x;

    if (blockIdx.x < 64) {
        // ---------------- decoder role ----------------
        __half (*WhS)[520]  = (__half(*)[520])(dsm + D_WH_OFF);
        __half (*hS)[520]   = (__half(*)[520])(dsm + D_HS_OFF);
        __half* aW1s        = (__half*)(dsm + D_AW_OFF);
        __half* W1TS        = (__half*)(dsm + D_W1_OFF);
        float  (*zS)[36]    = (float(*)[36])(dsm + D_ZS_OFF);
        float  (*scS)[64]   = (float(*)[64])(dsm + D_SC_OFF);
        float  (*hW1s)[10]  = (float(*)[10])(dsm + D_HW_OFF);
        float  (*ctxS)[32]  = (float(*)[32])(dsm + D_CX_OFF);

        int chunk = blockIdx.x, d0 = chunk << 3;
        int lane = tid & 31, warp = tid >> 5;
        int gid = lane >> 2, tig = lane & 3;
        int mrow = (warp >> 2) << 4, ncol = (warp & 3) << 3;

        for (int idx = tid; idx < 32 * 512; idx += 256) {
            int j = idx >> 9, k = idx & 511;
            WhS[j][k] = __float2half(Whd[(size_t)k * G4U + (j >> 3) * DD + d0 + (j & 7)]);
        }
        for (int i = tid; i < D_AW_B / 16; i += 256)
            reinterpret_cast<uint4*>(aW1s)[i] = reinterpret_cast<const uint4*>(g_aW1H)[i];
        for (int j = 0; j < 10; j++)
            for (int k = tid; k < 512; k += 256)
                W1TS[j * 520 + k] = g_W1TH[j * 512 + k];

        float w2r[10];
#pragma unroll
        for (int j = 0; j < 10; j++) w2r[j] = W2[j];
        float b2s = b2[0];

        int cb = tid >> 3, cq = tid & 7, cj4 = cq >> 1, csh = cq & 1;
        const __half* ctx_base = g_aWxdH + (size_t)cb * G4U + chunk * 32 + cj4 * 8;

        int ub = tid >> 3, ud = tid & 7;
        float cst = 0.f;
        float bdv[4];
#pragma unroll
        for (int gg = 0; gg < 4; gg++) bdv[gg] = bd[gg * DD + d0 + ud];

        __syncthreads();

        for (int t = 0; t < TT; t++) {
            if (t) {
                bar_spread(g_dctr, t, chunk & 7);
#pragma unroll
                for (int i = tid; i < 32 * 64; i += 256) {
                    int b = i >> 6, k8 = (i & 63) << 3;
                    uint4 v = *reinterpret_cast<const uint4*>(
                        &g_HdH[(size_t)((t - 1) * BB + b) * DD + k8]);
                    *reinterpret_cast<uint4*>(&hS[b][k8]) = v;
                }
                __syncthreads();
                for (int p = tid; p < 320; p += 256) {
                    int b = p / 10, j = p % 10;
                    const __half2* wt = reinterpret_cast<const __half2*>(&W1TS[j * 520]);
                    const __half2* hb = reinterpret_cast<const __half2*>(&hS[b][0]);
                    float a0 = 0.f, a1 = 0.f;
#pragma unroll 8
                    for (int k2 = 0; k2 < 256; k2 += 2) {
                        float2 w0 = __half22float2(wt[k2]),     h0 = __half22float2(hb[k2]);
                        float2 w1 = __half22float2(wt[k2 + 1]), h1 = __half22float2(hb[k2 + 1]);
                        a0 += h0.x * w0.x + h0.y * w0.y;
                        a1 += h1.x * w1.x + h1.y * w1.y;
                    }
                    hW1s[b][j] = a0 + a1;
                }
            } else {
                for (int p = tid; p < 320; p += 256) hW1s[p / 10][p % 10] = 0.f;
            }
            __syncthreads();
            for (int p = tid; p < 2048; p += 256) {
                int b = p & 31;
                const __half* aw = &aW1s[p * 12];
                float v = b2s;
#pragma unroll
                for (int j = 0; j < 10; j++)
                    v += tanh_fast(__half2float(aw[j]) + hW1s[b][j]) * w2r[j];
                scS[b][p >> 5] = fmaxf(v, 0.f);
            }
            __syncthreads();
            {
                int b = tid >> 3, g8 = tid & 7;
                float vv[8];
                float m = -1e30f;
#pragma unroll
                for (int q = 0; q < 8; q++) { vv[q] = scS[b][g8 * 8 + q]; m = fmaxf(m, vv[q]); }
#pragma unroll
                for (int o = 1; o < 8; o <<= 1) m = fmaxf(m, __shfl_xor_sync(0xffffffffu, m, o));
                float sm = 0.f;
#pragma unroll
                for (int q = 0; q < 8; q++) { vv[q] = __expf(vv[q] - m); sm += vv[q]; }
#pragma unroll
                for (int o = 1; o < 8; o <<= 1) sm += __shfl_xor_sync(0xffffffffu, sm, o);
                float inv = 1.f / sm;
#pragma unroll
                for (int q = 0; q < 8; q++) scS[b][g8 * 8 + q] = vv[q] * inv;
            }
            __syncthreads();
            float ca[8] = {};
            {
                int s0 = csh << 5;
#pragma unroll 8
                for (int s5 = s0; s5 < s0 + 32; s5++) {
                    float sc = scS[cb][s5];
                    uint4 v = *reinterpret_cast<const uint4*>(ctx_base + (size_t)s5 * BB * G4U);
                    float2 f0 = __half22float2(*(const __half2*)&v.x);
                    float2 f1 = __half22float2(*(const __half2*)&v.y);
                    float2 f2 = __half22float2(*(const __half2*)&v.z);
                    float2 f3 = __half22float2(*(const __half2*)&v.w);
                    ca[0] += sc * f0.x; ca[1] += sc * f0.y;
                    ca[2] += sc * f1.x; ca[3] += sc * f1.y;
                    ca[4] += sc * f2.x; ca[5] += sc * f2.y;
                    ca[6] += sc * f3.x; ca[7] += sc * f3.y;
                }
            }
#pragma unroll
            for (int q = 0; q < 8; q++) ca[q] += __shfl_xor_sync(0xffffffffu, ca[q], 1);
            if (csh == 0) {
#pragma unroll
                for (int q = 0; q < 8; q++) ctxS[cb][cj4 * 8 + q] = ca[q];
            }
            if (t) {
                float ac0[4] = {}, ac1[4] = {};
#pragma unroll 8
                for (int ks = 0; ks < 256; ks += 16) {
                    int ks2 = ks + 256;
                    uint32_t b0 = lds32(&WhS[ncol + gid][ks + 2 * tig]);
                    uint32_t b1 = lds32(&WhS[ncol + gid][ks + 2 * tig + 8]);
                    uint32_t a0 = lds32(&hS[mrow + gid    ][ks + 2 * tig]);
                    uint32_t a1 = lds32(&hS[mrow + gid + 8][ks + 2 * tig]);
                    uint32_t a2 = lds32(&hS[mrow + gid    ][ks + 2 * tig + 8]);
                    uint32_t a3 = lds32(&hS[mrow + gid + 8][ks + 2 * tig + 8]);
                    mma16h(ac0, a0, a1, a2, a3, b0, b1);
                    uint32_t c0 = lds32(&WhS[ncol + gid][ks2 + 2 * tig]);
                    uint32_t c1 = lds32(&WhS[ncol + gid][ks2 + 2 * tig + 8]);
                    uint32_t e0 = lds32(&hS[mrow + gid    ][ks2 + 2 * tig]);
                    uint32_t e1 = lds32(&hS[mrow + gid + 8][ks2 + 2 * tig]);
                    uint32_t e2 = lds32(&hS[mrow + gid    ][ks2 + 2 * tig + 8]);
                    uint32_t e3 = lds32(&hS[mrow + gid + 8][ks2 + 2 * tig + 8]);
                    mma16h(ac1, e0, e1, e2, e3, c0, c1);
                }
                zS[mrow + gid    ][ncol + 2 * tig    ] = ac0[0] + ac1[0];
                zS[mrow + gid    ][ncol + 2 * tig + 1] = ac0[1] + ac1[1];
                zS[mrow + gid + 8][ncol + 2 * tig    ] = ac0[2] + ac1[2];
                zS[mrow + gid + 8][ncol + 2 * tig + 1] = ac0[3] + ac1[3];
            }
            __syncthreads();
            {
                float z[4];
#pragma unroll
                for (int gg = 0; gg < 4; gg++) {
                    float zz = ctxS[ub][gg * 8 + ud] + bdv[gg];
                    if (t) zz += zS[ub][gg * 8 + ud];
                    z[gg] = zz;
                }
                float ct = sigf(z[1]) * cst + sigf(z[0]) * tanh_fast(z[2]);
                float h  = sigf(z[3]) * tanh_fast(ct);
                cst = ct;
                g_HdH[(size_t)(t * BB + ub) * DD + d0 + ud] = __float2half(h);
            }
            // signal step completion to gemm role
            __syncthreads();
            if (tid == 0)
                asm volatile("red.release.gpu.global.add.s32 [%0], 1;" :: "l"(&g_dprog) : "memory");
        }
        __syncthreads();
        if (tid == 0) {
            __threadfence();
            if (atomicAdd(&g_dfin, 1) == 63) {
                for (int i = 0; i < 256; i++) g_dctr[i] = 0;
                g_dfin = 0;
            }
        }
        __syncthreads();
    }

    // ---------------- gemm role (all blocks; decoder blocks join after finishing) ----------------
    for (;;) {
        if (tid == 0) s_tile = atomicAdd(&g_tile, 1);
        __syncthreads();
        int tile = s_tile;
        __syncthreads();
        if (tile >= NTILES) break;
        int mt5 = tile / 250, nt5 = tile % 250;
        __syncthreads();
        if (tid == 0) {
            int thr = 256 * (mt5 + 1);
            int v;
            do {
                asm volatile("ld.acquire.gpu.global.b32 %0, [%1];" : "=r"(v) : "l"(&g_dprog) : "memory");
            } while (v < thr);
        }
        __syncthreads();
        gemm_tile(dsm, bo, out, mt5 << 7, nt5 << 7);
    }
    if (tid == 0) {
        if (atomicAdd(&g_gfin, 1) == 147) {
            g_tile = 0;
            g_gfin = 0;
            g_dprog = 0;
        }
    }
}

// ---------------- normalize: out = exp / rowsum ----------------
__global__ void k_norm(float* __restrict__ out) {
    int r = blockIdx.x;
    float inv = 1.f / g_rowsum[r];
    float4* p = reinterpret_cast<float4*>(out + (size_t)r * VV);
    for (int i = threadIdx.x; i < VV / 4; i += 256) {
        float4 v = p[i];
        v.x *= inv; v.y *= inv; v.z *= inv; v.w *= inv;
        p[i] = v;
    }
}

// ---------------- host driver ----------------
extern "C" void kernel_launch(void* const* d_in, const int* in_sizes, int n_in,
                              void* d_out, int out_size)
{
    (void)in_sizes; (void)n_in; (void)out_size;
    const int*   x   = (const int*)  d_in[0];
    const float* emb = (const float*)d_in[1];
    const float* Wxf = (const float*)d_in[2];
    const float* Whf = (const float*)d_in[3];
    const float* bf  = (const float*)d_in[4];
    const float* Wxb = (const float*)d_in[5];
    const float* Whb = (const float*)d_in[6];
    const float* bbv = (const float*)d_in[7];
    const float* W1  = (const float*)d_in[8];
    const float* b1  = (const float*)d_in[9];
    const float* W2  = (const float*)d_in[10];
    const float* b2  = (const float*)d_in[11];
    const float* Wxd = (const float*)d_in[12];
    const float* Whd = (const float*)d_in[13];
    const float* bd  = (const float*)d_in[14];
    const float* Wo  = (const float*)d_in[15];
    const float* bo  = (const float*)d_in[16];
    float* out = (float*)d_out;

    float *p_xe, *p_Zf, *p_Zb, *p_a;
    __half *p_aWxdH;
    cudaGetSymbolAddress((void**)&p_xe,    g_xe);
    cudaGetSymbolAddress((void**)&p_Zf,    g_Zf);
    cudaGetSymbolAddress((void**)&p_Zb,    g_Zb);
    cudaGetSymbolAddress((void**)&p_a,     g_a);
    cudaGetSymbolAddress((void**)&p_aWxdH, g_aWxdH);

    cudaFuncSetAttribute(k_gemm,     cudaFuncAttributeMaxDynamicSharedMemorySize, 75776);
    cudaFuncSetAttribute(k_encoder,  cudaFuncAttributeMaxDynamicSharedMemorySize, E_SMEM);
    cudaFuncSetAttribute(k_dec_gemm, cudaFuncAttributeMaxDynamicSharedMemorySize, D_SMEM);

    k_embed<<<NTOK, 64>>>(x, emb);
    k_cvt_wo<<<dim3(VV / 32, DD / 32), dim3(32, 8)>>>(Wo);
    k_gemm<<<dim3(G4U / 128, NTOK / 128), 256, 75776>>>(p_xe, Wxf, bf,  p_Zf, nullptr, NTOK, G4U, EE);
    k_gemm<<<dim3(G4U / 128, NTOK / 128), 256, 75776>>>(p_xe, Wxb, bbv, p_Zb, nullptr, NTOK, G4U, EE);
    k_encoder<<<128, 256, E_SMEM>>>(Whf, Whb);
    k_gemm<<<dim3(G4U / 128, NTOK / 128), 256, 75776>>>(p_a, Wxd, nullptr, nullptr, p_aWxdH, NTOK, G4U, G2U);
    k_aw1<<<NTOK, 128>>>(W1, b1);
    k_w1t<<<10, 512>>>(W1);
    k_dec_gemm<<<148, 256, D_SMEM>>>(W2, b2, Whd, bd, bo, out);
    k_norm<<<NTOK, 256>>>(out);
}

// round 13
// speedup vs baseline: 1.2897x; 1.1441x over previous
#include <cuda_runtime.h>
#include <cuda_fp16.h>
#include <cstdint>

#define BB   32
#define TT   64
#define EE   256
#define UU   512
#define DD   512
#define VV   32000
#define NTOK 2048
#define G4U  2048
#define G2U  1024
#define NTILES 4000          // (2048/128) * (32000/128)

// ---------------- scratch ----------------
__device__ float  g_xe   [NTOK * EE];
__device__ float  g_Zf   [NTOK * G4U];
__device__ float  g_Zb   [NTOK * G4U];
__device__ float  g_a    [NTOK * G2U];
__device__ __half g_aH   [NTOK * G2U];
__device__ __half g_aW1H [NTOK * 12];
__device__ __half g_aWxdH[NTOK * G4U];
__device__ __half g_HdH  [NTOK * DD];
__device__ __half g_WoH  [VV * DD];
__device__ __half g_W1TH [10 * 512];
__device__ float  g_rowsum[NTOK];
__device__ int    g_ebar[2][TT];
__device__ int    g_efin[2];
__device__ int    g_dbar[TT];
__device__ int    g_dfin;
__device__ int    g_dprog;   // decoder step completion counter (64 per step)
__device__ int    g_tile;    // gemm tile dispenser
__device__ int    g_gfin;    // gemm role finish counter

__device__ __forceinline__ float sigf(float x) { return 1.f / (1.f + __expf(-x)); }
__device__ __forceinline__ float tanh_fast(float x) {
    float r; asm("tanh.approx.f32 %0, %1;" : "=f"(r) : "f"(x)); return r;
}

__device__ __forceinline__ void bar_sync(int* slot, int n) {
    __syncthreads();
    if (threadIdx.x == 0) {
        asm volatile("red.release.gpu.global.add.s32 [%0], 1;" :: "l"(slot) : "memory");
        int v;
        do {
            asm volatile("ld.acquire.gpu.global.b32 %0, [%1];" : "=r"(v) : "l"(slot) : "memory");
        } while (v < n);
    }
    __syncthreads();
}

__device__ __forceinline__ void mma8(float* c, uint32_t a0, uint32_t a1, uint32_t a2, uint32_t a3,
                                     uint32_t b0, uint32_t b1) {
    asm volatile(
        "mma.sync.aligned.m16n8k8.row.col.f32.tf32.tf32.f32 "
        "{%0,%1,%2,%3}, {%4,%5,%6,%7}, {%8,%9}, {%0,%1,%2,%3};\n"
        : "+f"(c[0]), "+f"(c[1]), "+f"(c[2]), "+f"(c[3])
        : "r"(a0), "r"(a1), "r"(a2), "r"(a3), "r"(b0), "r"(b1));
}

__device__ __forceinline__ void mma16h(float* c, uint32_t a0, uint32_t a1, uint32_t a2, uint32_t a3,
                                       uint32_t b0, uint32_t b1) {
    asm volatile(
        "mma.sync.aligned.m16n8k16.row.col.f32.f16.f16.f32 "
        "{%0,%1,%2,%3}, {%4,%5,%6,%7}, {%8,%9}, {%0,%1,%2,%3};\n"
        : "+f"(c[0]), "+f"(c[1]), "+f"(c[2]), "+f"(c[3])
        : "r"(a0), "r"(a1), "r"(a2), "r"(a3), "r"(b0), "r"(b1));
}

__device__ __forceinline__ uint32_t lds32(const __half* p) { return *(const uint32_t*)p; }

// ---------------- embedding gather + rowsum zero ----------------
__global__ void k_embed(const int* __restrict__ x, const float* __restrict__ emb) {
    int row = blockIdx.x;
    int t = row >> 5, b = row & 31;
    int tok = x[b * TT + t];
    const float4* src = reinterpret_cast<const float4*>(emb + (size_t)tok * EE);
    float4* dst = reinterpret_cast<float4*>(g_xe + (size_t)row * EE);
    dst[threadIdx.x] = src[threadIdx.x];
    if (threadIdx.x == 0) g_rowsum[row] = 0.f;
}

// ---------------- Wo convert + transpose ----------------
__global__ void k_cvt_wo(const float* __restrict__ Wo) {
    __shared__ float t[32][33];
    int n0 = blockIdx.x << 5, k0 = blockIdx.y << 5;
    for (int i = threadIdx.y; i < 32; i += 8)
        t[i][threadIdx.x] = Wo[(size_t)(k0 + i) * VV + n0 + threadIdx.x];
    __syncthreads();
    for (int i = threadIdx.y; i < 32; i += 8)
        g_WoH[(size_t)(n0 + i) * DD + k0 + threadIdx.x] = __float2half(t[threadIdx.x][i]);
}

// ---------------- W1 decoder-half transpose ----------------
__global__ void k_w1t(const float* __restrict__ W1) {
    int j = blockIdx.x;
    for (int k = threadIdx.x; k < 512; k += blockDim.x)
        g_W1TH[j * 512 + k] = __float2half(W1[(size_t)(G2U + k) * 10 + j]);
}

// ---------------- tf32 GEMM (double-buffered); Ch!=null -> permuted half output ----------------
// gridDim.z == 2 selects (A,B,bias,C) vs (A,B2,bias2,C2) for the fused Z launch.
__global__ __launch_bounds__(256) void k_gemm(
    const float* __restrict__ A, const float* __restrict__ B,
    const float* __restrict__ bias, float* __restrict__ C, __half* __restrict__ Ch,
    const float* __restrict__ B2, const float* __restrict__ bias2, float* __restrict__ C2,
    int M, int N, int K)
{
    extern __shared__ char gsm[];
    uint32_t (*As)[128][40] = (uint32_t(*)[128][40])gsm;
    uint32_t (*Bs)[32][136] = (uint32_t(*)[32][136])(gsm + 2 * 128 * 40 * 4);
    if (blockIdx.z == 1) { B = B2; bias = bias2; C = C2; }
    int tid = threadIdx.x, lane = tid & 31, warp = tid >> 5;
    int gid = lane >> 2, tig = lane & 3;
    int wm = warp & 3, wn = warp >> 2;
    int m0 = blockIdx.y << 7, n0 = blockIdx.x << 7;
    int ntile = K >> 5;
    float acc[2][8][4] = {};

    auto issue = [&](int kt) {
        int st = kt & 1;
        int k0 = kt << 5;
#pragma unroll
        for (int i = 0; i < 4; i++) {
            int idx = tid + (i << 8);
            int r = idx >> 3, c4 = (idx & 7) << 2;
            uint32_t d = (uint32_t)__cvta_generic_to_shared(&As[st][r][c4]);
            const float* s = A + (size_t)(m0 + r) * K + k0 + c4;
            asm volatile("cp.async.cg.shared.global [%0], [%1], 16;\n" :: "r"(d), "l"(s));
        }
#pragma unroll
        for (int i = 0; i < 4; i++) {
            int idx = tid + (i << 8);
            int r = idx >> 5, c4 = (idx & 31) << 2;
            uint32_t d = (uint32_t)__cvta_generic_to_shared(&Bs[st][r][c4]);
            const float* s = B + (size_t)(k0 + r) * N + n0 + c4;
            asm volatile("cp.async.cg.shared.global [%0], [%1], 16;\n" :: "r"(d), "l"(s));
        }
        asm volatile("cp.async.commit_group;\n");
    };

    issue(0);
    for (int kt = 0; kt < ntile; kt++) {
        if (kt + 1 < ntile) { issue(kt + 1); asm volatile("cp.async.wait_group 1;\n"); }
        else                 { asm volatile("cp.async.wait_group 0;\n"); }
        __syncthreads();
        int st = kt & 1;
#pragma unroll
        for (int kk = 0; kk < 32; kk += 8) {
            uint32_t af[2][4];
#pragma unroll
            for (int mt = 0; mt < 2; mt++) {
                int rb = (wm << 5) + (mt << 4);
                af[mt][0] = As[st][rb + gid    ][kk + tig];
                af[mt][1] = As[st][rb + gid + 8][kk + tig];
                af[mt][2] = As[st][rb + gid    ][kk + tig + 4];
                af[mt][3] = As[st][rb + gid + 8][kk + tig + 4];
            }
#pragma unroll
            for (int nt = 0; nt < 8; nt++) {
                uint32_t b0 = Bs[st][kk + tig    ][(wn << 6) + (nt << 3) + gid];
                uint32_t b1 = Bs[st][kk + tig + 4][(wn << 6) + (nt << 3) + gid];
#pragma unroll
                for (int mt = 0; mt < 2; mt++)
                    mma8(acc[mt][nt], af[mt][0], af[mt][1], af[mt][2], af[mt][3], b0, b1);
            }
        }
        __syncthreads();
    }
#pragma unroll
    for (int mt = 0; mt < 2; mt++) {
#pragma unroll
        for (int nt = 0; nt < 8; nt++) {
            int col = n0 + (wn << 6) + (nt << 3) + (tig << 1);
            int r0 = m0 + (wm << 5) + (mt << 4) + gid;
            int r1 = r0 + 8;
            if (Ch) {
                int d = col & 511, gate = col >> 9;
                int nc = ((d >> 3) << 5) + (gate << 3) + (d & 7);
                *reinterpret_cast<__half2*>(Ch + (size_t)r0 * N + nc) =
                    __floats2half2_rn(acc[mt][nt][0], acc[mt][nt][1]);
                *reinterpret_cast<__half2*>(Ch + (size_t)r1 * N + nc) =
                    __floats2half2_rn(acc[mt][nt][2], acc[mt][nt][3]);
            } else {
                float b0v = bias ? bias[col]     : 0.f;
                float b1v = bias ? bias[col + 1] : 0.f;
                float2 v0 = make_float2(acc[mt][nt][0] + b0v, acc[mt][nt][1] + b1v);
                float2 v1 = make_float2(acc[mt][nt][2] + b0v, acc[mt][nt][3] + b1v);
                *reinterpret_cast<float2*>(C + (size_t)r0 * N + col) = v0;
                *reinterpret_cast<float2*>(C + (size_t)r1 * N + col) = v1;
            }
        }
    }
}

// ---------------- persistent fp16 encoder: 128 blocks (64/dir), 8 dims each ----------------
#define E_WH_B (32 * 520 * 2)
#define E_HS_B (32 * 520 * 2)
#define E_ZS_B (32 * 36 * 4)
#define E_SMEM (E_WH_B + E_HS_B + E_ZS_B)

__global__ __launch_bounds__(256) void k_encoder(const float* __restrict__ Whf,
                                                 const float* __restrict__ Whb)
{
    extern __shared__ char esm[];
    __half (*WhS)[520] = (__half(*)[520])esm;
    __half (*hS)[520]  = (__half(*)[520])(esm + E_WH_B);
    float  (*zS)[36]   = (float(*)[36])(esm + E_WH_B + E_HS_B);

    int dir = blockIdx.x >> 6, chunk = blockIdx.x & 63, d0 = chunk << 3;
    const float* Wh = dir ? Whb : Whf;
    const float* Z  = dir ? g_Zb : g_Zf;
    int tid = threadIdx.x, lane = tid & 31, warp = tid >> 5;
    int gid = lane >> 2, tig = lane & 3;
    int mrow = (warp >> 2) << 4, ncol = (warp & 3) << 3;
    int* bar = &g_ebar[dir][0];

    for (int idx = tid; idx < 32 * 512; idx += 256) {
        int j = idx >> 9, k = idx & 511;
        WhS[j][k] = __float2half(Wh[(size_t)k * G4U + (j >> 3) * UU + d0 + (j & 7)]);
    }

    int ub = tid >> 3, ud = tid & 7;
    float cst = 0.f;

    for (int s = 0; s < TT; s++) {
        int t = dir ? (TT - 1 - s) : s;
        size_t zrow = (size_t)(t * BB + ub) * G4U + d0 + ud;
        float zv0 = Z[zrow];
        float zv1 = Z[zrow + UU];
        float zv2 = Z[zrow + 2 * UU];
        float zv3 = Z[zrow + 3 * UU];
        if (s) {
            bar_sync(&bar[s], 64);
            int tp = dir ? (t + 1) : (t - 1);
#pragma unroll
            for (int i = tid; i < 32 * 64; i += 256) {
                int b = i >> 6, k8 = (i & 63) << 3;
                uint4 v = *reinterpret_cast<const uint4*>(
                    &g_aH[(size_t)(tp * BB + b) * G2U + dir * UU + k8]);
                *reinterpret_cast<uint4*>(&hS[b][k8]) = v;
            }
            __syncthreads();
            float ac0[4] = {}, ac1[4] = {};
#pragma unroll 8
            for (int ks = 0; ks < 256; ks += 16) {
                int ks2 = ks + 256;
                uint32_t b0 = lds32(&WhS[ncol + gid][ks + 2 * tig]);
                uint32_t b1 = lds32(&WhS[ncol + gid][ks + 2 * tig + 8]);
                uint32_t a0 = lds32(&hS[mrow + gid    ][ks + 2 * tig]);
                uint32_t a1 = lds32(&hS[mrow + gid + 8][ks + 2 * tig]);
                uint32_t a2 = lds32(&hS[mrow + gid    ][ks + 2 * tig + 8]);
                uint32_t a3 = lds32(&hS[mrow + gid + 8][ks + 2 * tig + 8]);
                mma16h(ac0, a0, a1, a2, a3, b0, b1);
                uint32_t c0 = lds32(&WhS[ncol + gid][ks2 + 2 * tig]);
                uint32_t c1 = lds32(&WhS[ncol + gid][ks2 + 2 * tig + 8]);
                uint32_t d0r = lds32(&hS[mrow + gid    ][ks2 + 2 * tig]);
                uint32_t d1r = lds32(&hS[mrow + gid + 8][ks2 + 2 * tig]);
                uint32_t d2r = lds32(&hS[mrow + gid    ][ks2 + 2 * tig + 8]);
                uint32_t d3r = lds32(&hS[mrow + gid + 8][ks2 + 2 * tig + 8]);
                mma16h(ac1, d0r, d1r, d2r, d3r, c0, c1);
            }
            zS[mrow + gid    ][ncol + 2 * tig    ] = ac0[0] + ac1[0];
            zS[mrow + gid    ][ncol + 2 * tig + 1] = ac0[1] + ac1[1];
            zS[mrow + gid + 8][ncol + 2 * tig    ] = ac0[2] + ac1[2];
            zS[mrow + gid + 8][ncol + 2 * tig + 1] = ac0[3] + ac1[3];
            __syncthreads();
        }
        {
            float zi = zv0, zf = zv1, zg = zv2, zo = zv3;
            if (s) {
                zi += zS[ub][ud]; zf += zS[ub][8 + ud];
                zg += zS[ub][16 + ud]; zo += zS[ub][24 + ud];
            }
            float ct = sigf(zf) * cst + sigf(zi) * tanh_fast(zg);
            float h  = sigf(zo) * tanh_fast(ct);
            cst = ct;
            size_t oi = (size_t)(t * BB + ub) * G2U + dir * UU + d0 + ud;
            g_a[oi]  = h;
            g_aH[oi] = __float2half(h);
        }
    }
    __syncthreads();
    if (tid == 0) {
        __threadfence();
        if (atomicAdd(&g_efin[dir], 1) == 63) {
            for (int i = 0; i < TT; i++) bar[i] = 0;
            g_efin[dir] = 0;
        }
    }
}

// ---------------- aW1 = a @ W1[:1024] + b1 -> half, pitch 12 ----------------
__global__ __launch_bounds__(128) void k_aw1(const float* __restrict__ W1,
                                             const float* __restrict__ b1)
{
    __shared__ float red[128][10];
    int r = blockIdx.x;
    int tid = threadIdx.x;
    float acc[10];
#pragma unroll
    for (int j = 0; j < 10; j++) acc[j] = 0.f;
    for (int k = tid; k < G2U; k += 128) {
        float av = g_a[(size_t)r * G2U + k];
#pragma unroll
        for (int j = 0; j < 10; j++) acc[j] += av * W1[(size_t)k * 10 + j];
    }
#pragma unroll
    for (int j = 0; j < 10; j++) red[tid][j] = acc[j];
    __syncthreads();
    for (int s = 64; s > 0; s >>= 1) {
        if (tid < s)
#pragma unroll
            for (int j = 0; j < 10; j++) red[tid][j] += red[tid + s][j];
        __syncthreads();
    }
    if (tid < 12)
        g_aW1H[(size_t)r * 12 + tid] = __float2half((tid < 10) ? (red[0][tid] + b1[tid]) : 0.f);
}

// ---------------- fused decoder + logits GEMM (exp epilogue) ----------------
#define D_WH_OFF  0
#define D_WH_B    (32 * 520 * 2)
#define D_HS_OFF  (D_WH_OFF + D_WH_B)
#define D_HS_B    (32 * 520 * 2)
#define D_AW_OFF  (D_HS_OFF + D_HS_B)
#define D_AW_B    (2048 * 12 * 2)
#define D_W1_OFF  (D_AW_OFF + D_AW_B)
#define D_W1_B    (10 * 520 * 2)
#define D_ZS_OFF  (D_W1_OFF + D_W1_B)
#define D_ZS_B    (32 * 36 * 4)
#define D_SC_OFF  (D_ZS_OFF + D_ZS_B)
#define D_SC_B    (32 * 64 * 4)
#define D_HW_OFF  (D_SC_OFF + D_SC_B)
#define D_HW_B    (32 * 10 * 4)
#define D_CX_OFF  (D_HW_OFF + D_HW_B)
#define D_CX_B    (32 * 32 * 4)
#define D_SMEM    (D_CX_OFF + D_CX_B)
#define G_SRS_OFF (3 * 2 * 128 * 40 * 2)   // 61440, after f16 gemm buffers (< D_SMEM)

__device__ void gemm_tile(char* fsm, const float* __restrict__ bias,
                          float* __restrict__ C, int m0, int n0)
{
    __half (*As)[128][40] = (__half(*)[128][40])fsm;
    __half (*Bs)[128][40] = (__half(*)[128][40])(fsm + 3 * 128 * 40 * 2);
    float* srs = (float*)(fsm + G_SRS_OFF);
    const __half* A  = g_HdH;
    const __half* Bt = g_WoH;
    const int K = DD;
    int tid = threadIdx.x, lane = tid & 31, warp = tid >> 5;
    int gid = lane >> 2, tig = lane & 3;
    int wm = warp & 3, wn = warp >> 2;
    float acc[2][8][4] = {};

    if (tid < 128) srs[tid] = 0.f;

    auto issue = [&](int kt) {
        int st = kt % 3;
        int k0 = kt << 5;
#pragma unroll
        for (int i = 0; i < 2; i++) {
            int idx = tid + (i << 8);
            int r = idx >> 2, c = (idx & 3) << 3;
            uint32_t d = (uint32_t)__cvta_generic_to_shared(&As[st][r][c]);
            const __half* s = A + (size_t)(m0 + r) * K + k0 + c;
            asm volatile("cp.async.cg.shared.global [%0], [%1], 16;\n" :: "r"(d), "l"(s));
        }
#pragma unroll
        for (int i = 0; i < 2; i++) {
            int idx = tid + (i << 8);
            int r = idx >> 2, c = (idx & 3) << 3;
            uint32_t d = (uint32_t)__cvta_generic_to_shared(&Bs[st][r][c]);
            const __half* s = Bt + (size_t)(n0 + r) * K + k0 + c;
            asm volatile("cp.async.cg.shared.global [%0], [%1], 16;\n" :: "r"(d), "l"(s));
        }
        asm volatile("cp.async.commit_group;\n");
    };

    issue(0); issue(1);
#pragma unroll 1
    for (int kt = 0; kt < 16; kt++) {
        if (kt + 2 < 16)      { issue(kt + 2); asm volatile("cp.async.wait_group 2;\n"); }
        else if (kt + 1 < 16) { asm volatile("cp.async.wait_group 1;\n"); }
        else                  { asm volatile("cp.async.wait_group 0;\n"); }
        __syncthreads();
        int st = kt % 3;
#pragma unroll
        for (int ks = 0; ks < 32; ks += 16) {
            uint32_t af[2][4];
#pragma unroll
            for (int mt = 0; mt < 2; mt++) {
                int rb = (wm << 5) + (mt << 4);
                af[mt][0] = *(const uint32_t*)&As[st][rb + gid    ][ks + 2 * tig];
                af[mt][1] = *(const uint32_t*)&As[st][rb + gid + 8][ks + 2 * tig];
                af[mt][2] = *(const uint32_t*)&As[st][rb + gid    ][ks + 2 * tig + 8];
                af[mt][3] = *(const uint32_t*)&As[st][rb + gid + 8][ks + 2 * tig + 8];
            }
#pragma unroll
            for (int nt = 0; nt < 8; nt++) {
                int n = (wn << 6) + (nt << 3) + gid;
                uint32_t b0 = *(const uint32_t*)&Bs[st][n][ks + 2 * tig];
                uint32_t b1 = *(const uint32_t*)&Bs[st][n][ks + 2 * tig + 8];
#pragma unroll
                for (int mt = 0; mt < 2; mt++)
                    mma16h(acc[mt][nt], af[mt][0], af[mt][1], af[mt][2], af[mt][3], b0, b1);
            }
        }
        __syncthreads();
    }
    float rsum[2][2] = {};
#pragma unroll
    for (int mt = 0; mt < 2; mt++) {
#pragma unroll
        for (int nt = 0; nt < 8; nt++) {
            int col = n0 + (wn << 6) + (nt << 3) + (tig << 1);
            float b0v = bias[col], b1v = bias[col + 1];
            int r0 = m0 + (wm << 5) + (mt << 4) + gid;
            int r1 = r0 + 8;
            int or0 = (r0 & 31) * TT + (r0 >> 5);
            int or1 = (r1 & 31) * TT + (r1 >> 5);
            float e0 = __expf(acc[mt][nt][0] + b0v);
            float e1 = __expf(acc[mt][nt][1] + b1v);
            float e2 = __expf(acc[mt][nt][2] + b0v);
            float e3 = __expf(acc[mt][nt][3] + b1v);
            rsum[mt][0] += e0 + e1;
            rsum[mt][1] += e2 + e3;
            *reinterpret_cast<float2*>(C + (size_t)or0 * VV + col) = make_float2(e0, e1);
            *reinterpret_cast<float2*>(C + (size_t)or1 * VV + col) = make_float2(e2, e3);
        }
    }
#pragma unroll
    for (int mt = 0; mt < 2; mt++) {
        int lr = (wm << 5) + (mt << 4) + gid;
        atomicAdd(&srs[lr],     rsum[mt][0]);
        atomicAdd(&srs[lr + 8], rsum[mt][1]);
    }
    __syncthreads();
    if (tid < 128) {
        int r = m0 + tid;
        int orr = (r & 31) * TT + (r >> 5);
        atomicAdd(&g_rowsum[orr], srs[tid]);
    }
    __syncthreads();
}

__global__ __launch_bounds__(256) void k_dec_gemm(
    const float* __restrict__ W2, const float* __restrict__ b2,
    const float* __restrict__ Whd, const float* __restrict__ bd,
    const float* __restrict__ bo, float* __restrict__ out)
{
    extern __shared__ char dsm[];
    __shared__ int s_tile;
    int tid = threadIdx.x;

    if (blockIdx.x < 64) {
        // ---------------- decoder role ----------------
        __half (*WhS)[520]  = (__half(*)[520])(dsm + D_WH_OFF);
        __half (*hS)[520]   = (__half(*)[520])(dsm + D_HS_OFF);
        __half* aW1s        = (__half*)(dsm + D_AW_OFF);
        __half* W1TS        = (__half*)(dsm + D_W1_OFF);
        float  (*zS)[36]    = (float(*)[36])(dsm + D_ZS_OFF);
        float  (*scS)[64]   = (float(*)[64])(dsm + D_SC_OFF);
        float  (*hW1s)[10]  = (float(*)[10])(dsm + D_HW_OFF);
        float  (*ctxS)[32]  = (float(*)[32])(dsm + D_CX_OFF);

        int chunk = blockIdx.x, d0 = chunk << 3;
        int lane = tid & 31, warp = tid >> 5;
        int gid = lane >> 2, tig = lane & 3;
        int mrow = (warp >> 2) << 4, ncol = (warp & 3) << 3;

        for (int idx = tid; idx < 32 * 512; idx += 256) {
            int j = idx >> 9, k = idx & 511;
            WhS[j][k] = __float2half(Whd[(size_t)k * G4U + (j >> 3) * DD + d0 + (j & 7)]);
        }
        for (int i = tid; i < D_AW_B / 16; i += 256)
            reinterpret_cast<uint4*>(aW1s)[i] = reinterpret_cast<const uint4*>(g_aW1H)[i];
        for (int j = 0; j < 10; j++)
            for (int k = tid; k < 512; k += 256)
                W1TS[j * 520 + k] = g_W1TH[j * 512 + k];

        float w2r[10];
#pragma unroll
        for (int j = 0; j < 10; j++) w2r[j] = W2[j];
        float b2s = b2[0];

        int cb = tid >> 3, cq = tid & 7, cj4 = cq >> 1, csh = cq & 1;
        const __half* ctx_base = g_aWxdH + (size_t)cb * G4U + chunk * 32 + cj4 * 8;

        int ub = tid >> 3, ud = tid & 7;
        float cst = 0.f;
        float bdv[4];
#pragma unroll
        for (int gg = 0; gg < 4; gg++) bdv[gg] = bd[gg * DD + d0 + ud];

        __syncthreads();

        for (int t = 0; t < TT; t++) {
            if (t) {
                bar_sync(&g_dbar[t], 64);
#pragma unroll
                for (int i = tid; i < 32 * 64; i += 256) {
                    int b = i >> 6, k8 = (i & 63) << 3;
                    uint4 v = *reinterpret_cast<const uint4*>(
                        &g_HdH[(size_t)((t - 1) * BB + b) * DD + k8]);
                    *reinterpret_cast<uint4*>(&hS[b][k8]) = v;
                }
                __syncthreads();
                for (int p = tid; p < 320; p += 256) {
                    int b = p / 10, j = p % 10;
                    const __half2* wt = reinterpret_cast<const __half2*>(&W1TS[j * 520]);
                    const __half2* hb = reinterpret_cast<const __half2*>(&hS[b][0]);
                    float a0 = 0.f, a1 = 0.f;
#pragma unroll 8
                    for (int k2 = 0; k2 < 256; k2 += 2) {
                        float2 w0 = __half22float2(wt[k2]),     h0 = __half22float2(hb[k2]);
                        float2 w1 = __half22float2(wt[k2 + 1]), h1 = __half22float2(hb[k2 + 1]);
                        a0 += h0.x * w0.x + h0.y * w0.y;
                        a1 += h1.x * w1.x + h1.y * w1.y;
                    }
                    hW1s[b][j] = a0 + a1;
                }
            } else {
                for (int p = tid; p < 320; p += 256) hW1s[p / 10][p % 10] = 0.f;
            }
            __syncthreads();
            for (int p = tid; p < 2048; p += 256) {
                int b = p & 31;
                const __half* aw = &aW1s[p * 12];
                float v = b2s;
#pragma unroll
                for (int j = 0; j < 10; j++)
                    v += tanh_fast(__half2float(aw[j]) + hW1s[b][j]) * w2r[j];
                scS[b][p >> 5] = fmaxf(v, 0.f);
            }
            __syncthreads();
            {
                int b = tid >> 3, g8 = tid & 7;
                float vv[8];
                float m = -1e30f;
#pragma unroll
                for (int q = 0; q < 8; q++) { vv[q] = scS[b][g8 * 8 + q]; m = fmaxf(m, vv[q]); }
#pragma unroll
                for (int o = 1; o < 8; o <<= 1) m = fmaxf(m, __shfl_xor_sync(0xffffffffu, m, o));
                float sm = 0.f;
#pragma unroll
                for (int q = 0; q < 8; q++) { vv[q] = __expf(vv[q] - m); sm += vv[q]; }
#pragma unroll
                for (int o = 1; o < 8; o <<= 1) sm += __shfl_xor_sync(0xffffffffu, sm, o);
                float inv = 1.f / sm;
#pragma unroll
                for (int q = 0; q < 8; q++) scS[b][g8 * 8 + q] = vv[q] * inv;
            }
            __syncthreads();
            float ca[8] = {};
            {
                int s0 = csh << 5;
#pragma unroll 8
                for (int s5 = s0; s5 < s0 + 32; s5++) {
                    float sc = scS[cb][s5];
                    uint4 v = *reinterpret_cast<const uint4*>(ctx_base + (size_t)s5 * BB * G4U);
                    float2 f0 = __half22float2(*(const __half2*)&v.x);
                    float2 f1 = __half22float2(*(const __half2*)&v.y);
                    float2 f2 = __half22float2(*(const __half2*)&v.z);
                    float2 f3 = __half22float2(*(const __half2*)&v.w);
                    ca[0] += sc * f0.x; ca[1] += sc * f0.y;
                    ca[2] += sc * f1.x; ca[3] += sc * f1.y;
                    ca[4] += sc * f2.x; ca[5] += sc * f2.y;
                    ca[6] += sc * f3.x; ca[7] += sc * f3.y;
                }
            }
#pragma unroll
            for (int q = 0; q < 8; q++) ca[q] += __shfl_xor_sync(0xffffffffu, ca[q], 1);
            if (csh == 0) {
#pragma unroll
                for (int q = 0; q < 8; q++) ctxS[cb][cj4 * 8 + q] = ca[q];
            }
            if (t) {
                float ac0[4] = {}, ac1[4] = {};
#pragma unroll 8
                for (int ks = 0; ks < 256; ks += 16) {
                    int ks2 = ks + 256;
                    uint32_t b0 = lds32(&WhS[ncol + gid][ks + 2 * tig]);
                    uint32_t b1 = lds32(&WhS[ncol + gid][ks + 2 * tig + 8]);
                    uint32_t a0 = lds32(&hS[mrow + gid    ][ks + 2 * tig]);
                    uint32_t a1 = lds32(&hS[mrow + gid + 8][ks + 2 * tig]);
                    uint32_t a2 = lds32(&hS[mrow + gid    ][ks + 2 * tig + 8]);
                    uint32_t a3 = lds32(&hS[mrow + gid + 8][ks + 2 * tig + 8]);
                    mma16h(ac0, a0, a1, a2, a3, b0, b1);
                    uint32_t c0 = lds32(&WhS[ncol + gid][ks2 + 2 * tig]);
                    uint32_t c1 = lds32(&WhS[ncol + gid][ks2 + 2 * tig + 8]);
                    uint32_t e0 = lds32(&hS[mrow + gid    ][ks2 + 2 * tig]);
                    uint32_t e1 = lds32(&hS[mrow + gid + 8][ks2 + 2 * tig]);
                    uint32_t e2 = lds32(&hS[mrow + gid    ][ks2 + 2 * tig + 8]);
                    uint32_t e3 = lds32(&hS[mrow + gid + 8][ks2 + 2 * tig + 8]);
                    mma16h(ac1, e0, e1, e2, e3, c0, c1);
                }
                zS[mrow + gid    ][ncol + 2 * tig    ] = ac0[0] + ac1[0];
                zS[mrow + gid    ][ncol + 2 * tig + 1] = ac0[1] + ac1[1];
                zS[mrow + gid + 8][ncol + 2 * tig    ] = ac0[2] + ac1[2];
                zS[mrow + gid + 8][ncol + 2 * tig + 1] = ac0[3] + ac1[3];
            }
            __syncthreads();
            {
                float z[4];
#pragma unroll
                for (int gg = 0; gg < 4; gg++) {
                    float zz = ctxS[ub][gg * 8 + ud] + bdv[gg];
                    if (t) zz += zS[ub][gg * 8 + ud];
                    z[gg] = zz;
                }
                float ct = sigf(z[1]) * cst + sigf(z[0]) * tanh_fast(z[2]);
                float h  = sigf(z[3]) * tanh_fast(ct);
                cst = ct;
                g_HdH[(size_t)(t * BB + ub) * DD + d0 + ud] = __float2half(h);
            }
            // signal step completion to gemm role
            __syncthreads();
            if (tid == 0)
                asm volatile("red.release.gpu.global.add.s32 [%0], 1;" :: "l"(&g_dprog) : "memory");
        }
        __syncthreads();
        if (tid == 0) {
            __threadfence();
            if (atomicAdd(&g_dfin, 1) == 63) {
                for (int i = 0; i < TT; i++) g_dbar[i] = 0;
                g_dfin = 0;
            }
        }
        __syncthreads();
    }

    // ---------------- gemm role (all blocks; decoder blocks join after finishing) ----------------
    for (;;) {
        if (tid == 0) s_tile = atomicAdd(&g_tile, 1);
        __syncthreads();
        int tile = s_tile;
        __syncthreads();
        if (tile >= NTILES) break;
        int mt5 = tile / 250, nt5 = tile % 250;
        __syncthreads();
        if (tid == 0) {
            int thr = 256 * (mt5 + 1);
            int v;
            do {
                asm volatile("ld.acquire.gpu.global.b32 %0, [%1];" : "=r"(v) : "l"(&g_dprog) : "memory");
            } while (v < thr);
        }
        __syncthreads();
        gemm_tile(dsm, bo, out, mt5 << 7, nt5 << 7);
    }
    if (tid == 0) {
        if (atomicAdd(&g_gfin, 1) == 147) {
            g_tile = 0;
            g_gfin = 0;
            g_dprog = 0;
        }
    }
}

// ---------------- normalize: out = exp / rowsum ----------------
__global__ void k_norm(float* __restrict__ out) {
    int r = blockIdx.x;
    float inv = 1.f / g_rowsum[r];
    float4* p = reinterpret_cast<float4*>(out + (size_t)r * VV);
    for (int i = threadIdx.x; i < VV / 4; i += 256) {
        float4 v = p[i];
        v.x *= inv; v.y *= inv; v.z *= inv; v.w *= inv;
        p[i] = v;
    }
}

// ---------------- host driver ----------------
extern "C" void kernel_launch(void* const* d_in, const int* in_sizes, int n_in,
                              void* d_out, int out_size)
{
    (void)in_sizes; (void)n_in; (void)out_size;
    const int*   x   = (const int*)  d_in[0];
    const float* emb = (const float*)d_in[1];
    const float* Wxf = (const float*)d_in[2];
    const float* Whf = (const float*)d_in[3];
    const float* bf  = (const float*)d_in[4];
    const float* Wxb = (const float*)d_in[5];
    const float* Whb = (const float*)d_in[6];
    const float* bbv = (const float*)d_in[7];
    const float* W1  = (const float*)d_in[8];
    const float* b1  = (const float*)d_in[9];
    const float* W2  = (const float*)d_in[10];
    const float* b2  = (const float*)d_in[11];
    const float* Wxd = (const float*)d_in[12];
    const float* Whd = (const float*)d_in[13];
    const float* bd  = (const float*)d_in[14];
    const float* Wo  = (const float*)d_in[15];
    const float* bo  = (const float*)d_in[16];
    float* out = (float*)d_out;

    float *p_xe, *p_Zf, *p_Zb, *p_a;
    __half *p_aWxdH;
    cudaGetSymbolAddress((void**)&p_xe,    g_xe);
    cudaGetSymbolAddress((void**)&p_Zf,    g_Zf);
    cudaGetSymbolAddress((void**)&p_Zb,    g_Zb);
    cudaGetSymbolAddress((void**)&p_a,     g_a);
    cudaGetSymbolAddress((void**)&p_aWxdH, g_aWxdH);

    cudaFuncSetAttribute(k_gemm,     cudaFuncAttributeMaxDynamicSharedMemorySize, 75776);
    cudaFuncSetAttribute(k_encoder,  cudaFuncAttributeMaxDynamicSharedMemorySize, E_SMEM);
    cudaFuncSetAttribute(k_dec_gemm, cudaFuncAttributeMaxDynamicSharedMemorySize, D_SMEM);

    k_embed<<<NTOK, 64>>>(x, emb);
    k_cvt_wo<<<dim3(VV / 32, DD / 32), dim3(32, 8)>>>(Wo);
    k_gemm<<<dim3(G4U / 128, NTOK / 128, 2), 256, 75776>>>(
        p_xe, Wxf, bf, p_Zf, nullptr, Wxb, bbv, p_Zb, NTOK, G4U, EE);
    k_encoder<<<128, 256, E_SMEM>>>(Whf, Whb);
    k_gemm<<<dim3(G4U / 128, NTOK / 128, 1), 256, 75776>>>(
        p_a, Wxd, nullptr, nullptr, p_aWxdH, nullptr, nullptr, nullptr, NTOK, G4U, G2U);
    k_aw1<<<NTOK, 128>>>(W1, b1);
    k_w1t<<<10, 512>>>(W1);
    k_dec_gemm<<<148, 256, D_SMEM>>>(W2, b2, Whd, bd, bo, out);
    k_norm<<<NTOK, 256>>>(out);
}